// round 14
// baseline (speedup 1.0000x reference)
#include <cuda_runtime.h>
#include <cuda_fp16.h>
#include <cstdint>

#define EPSF 1e-6f

constexpr int B_ = 8;
constexpr int S_ = 2048;
constexpr int T_ = 2048;
constexpr int E_ = 512;

constexpr int NSE = B_ * S_ * E_;               // 8388608
constexpr size_t NST = (size_t)B_ * S_ * T_;    // 33554432

// ---------------- scratch (device globals) ----------------
__device__ __half g_encH[NSE], g_encL[NSE];
__device__ __half g_emoH[NSE], g_emoL[NSE];
__device__ __half g_WqH[E_*E_], g_WqL[E_*E_];
__device__ __half g_WkH[E_*E_], g_WkL[E_*E_];
__device__ __half g_WvH[E_*E_], g_WvL[E_*E_];
__device__ __half g_WoH[E_*E_], g_WoL[E_*E_];
__device__ __half g_qH[NSE], g_qL[NSE];
__device__ __half g_kH[NSE], g_kL[NSE];
__device__ float  g_v[NSE];
__device__ __half g_vTH[NSE], g_vTL[NSE];
__device__ float  g_logits[NST];
__device__ __half g_pH[NST];
__device__ __half g_ctxH[NSE];
__device__ float  g_tmp[NSE];

// ---------------- helpers ----------------
__device__ __forceinline__ uint32_t smem_u32(const void* p) {
    uint32_t a;
    asm("{ .reg .u64 t; cvta.to.shared.u64 t, %1; cvt.u32.u64 %0, t; }" : "=r"(a) : "l"(p));
    return a;
}
#define CP16(dst, src) asm volatile("cp.async.cg.shared.global [%0], [%1], 16;" :: "r"(dst), "l"(src))
#define CP_COMMIT()    asm volatile("cp.async.commit_group;")
#define CP_WAIT0()     asm volatile("cp.async.wait_group 0;")

__device__ __forceinline__ void ldsm4(uint32_t& r0, uint32_t& r1, uint32_t& r2, uint32_t& r3, uint32_t a) {
    asm volatile("ldmatrix.sync.aligned.m8n8.x4.shared.b16 {%0,%1,%2,%3}, [%4];"
                 : "=r"(r0), "=r"(r1), "=r"(r2), "=r"(r3) : "r"(a));
}
__device__ __forceinline__ void mma16816(float* c, const uint32_t* a, const uint32_t* b) {
    asm volatile("mma.sync.aligned.m16n8k16.row.col.f32.f16.f16.f32 "
                 "{%0,%1,%2,%3}, {%4,%5,%6,%7}, {%8,%9}, {%0,%1,%2,%3};"
                 : "+f"(c[0]), "+f"(c[1]), "+f"(c[2]), "+f"(c[3])
                 : "r"(a[0]), "r"(a[1]), "r"(a[2]), "r"(a[3]), "r"(b[0]), "r"(b[1]));
}
__device__ __forceinline__ uint32_t pack_hi2(float x, float y) {
    unsigned short hx = __half_as_ushort(__float2half_rn(x));
    unsigned short hy = __half_as_ushort(__float2half_rn(y));
    return (uint32_t)hx | ((uint32_t)hy << 16);
}
__device__ __forceinline__ uint32_t pack_lo2(float x, float y) {
    float hx = __half2float(__float2half_rn(x));
    float hy = __half2float(__float2half_rn(y));
    unsigned short lx = __half_as_ushort(__float2half_rn(x - hx));
    unsigned short ly = __half_as_ushort(__float2half_rn(y - hy));
    return (uint32_t)lx | ((uint32_t)ly << 16);
}

// ---------------------------------------------------------------------------
// fp16-split GEMM, NT form, software-pipelined fragments.
// Block tile 128x128, BK=64, 256 threads (8 warps 2x4, warp tile 64x32),
// 2-stage cp.async SMEM + 2-deep register fragment pipeline:
// s-step s+1's ldmatrix issues BEFORE s's MMAs -> ldsm latency hidden.
// NPROD=3: AhBh+AhBl+AlBh. NPROD=2: AhBh+AhBl (A-lo never touched).
// EPI: 0 bias+split(hi,lo), 1 bias+f32, 2 mask+f32, 4 add+f32, 5 hi-only
// ---------------------------------------------------------------------------
template <int EPI, int NPROD>
__global__ void __launch_bounds__(256, 1) gemm_mma(
    const __half* __restrict__ Ah, const __half* __restrict__ Al,
    const __half* __restrict__ Bh, const __half* __restrict__ Bl,
    int K, int Nt,
    long sA, long sB, long sC,
    const float* __restrict__ bias,
    const int* __restrict__ mask,
    const float* __restrict__ add,
    float* __restrict__ Cf,
    __half* __restrict__ Ch, __half* __restrict__ Cl)
{
    extern __shared__ __align__(16) char dsm[];
    constexpr uint32_t ROWB = 144;                      // 64 fp16 (128B) + 16B pad
    constexpr uint32_t TILE = 128 * ROWB;               // 18432
    constexpr uint32_t OAH = 0;
    constexpr uint32_t OAL = TILE;                      // NPROD=3 only
    constexpr uint32_t OBH = (NPROD == 3) ? 2 * TILE : TILE;
    constexpr uint32_t OBL = OBH + TILE;
    constexpr uint32_t STAGE = OBL + TILE;              // 73728 / 55296

    const uint32_t smb = smem_u32(dsm);
    const int tid = threadIdx.x;
    const int lane = tid & 31;
    const int wid = tid >> 5;

    const int bm = blockIdx.y * 128;
    const int bn = blockIdx.x * 128;
    const long z = blockIdx.z;

    const __half* bAh = Ah + z * sA;
    const __half* bAl = (NPROD == 3) ? (Al + z * sA) : nullptr;
    const __half* bBh = Bh + z * sB;
    const __half* bBl = Bl + z * sB;

    // loader: each 128x64 fp16 tile = 1024 16B-chunks, 4 per thread
#define LOAD_STAGE(stg, k0) do {                                                             \
    uint32_t sb_ = smb + (uint32_t)(stg) * STAGE;                                            \
    _Pragma("unroll")                                                                        \
    for (int i_ = 0; i_ < 4; i_++) {                                                         \
        int id_ = tid + i_ * 256, r_ = id_ >> 3, s_ = id_ & 7;                               \
        CP16(sb_ + OAH + r_ * ROWB + s_ * 16, bAh + (size_t)(bm + r_) * K + (k0) + s_ * 8);  \
        if (NPROD == 3)                                                                      \
            CP16(sb_ + OAL + r_ * ROWB + s_ * 16, bAl + (size_t)(bm + r_) * K + (k0) + s_ * 8);\
        CP16(sb_ + OBH + r_ * ROWB + s_ * 16, bBh + (size_t)(bn + r_) * K + (k0) + s_ * 8);  \
        CP16(sb_ + OBL + r_ * ROWB + s_ * 16, bBl + (size_t)(bn + r_) * K + (k0) + s_ * 8);  \
    }                                                                                        \
} while (0)

    float acc[4][4][4];
#pragma unroll
    for (int i = 0; i < 4; i++)
#pragma unroll
        for (int j = 0; j < 4; j++)
#pragma unroll
            for (int t = 0; t < 4; t++) acc[i][j][t] = 0.0f;

    const int nk = K >> 6;
    LOAD_STAGE(0, 0);
    CP_COMMIT();

    const int m0w = (wid & 1) * 64;      // 2 warps in M
    const int n0w = (wid >> 1) * 32;     // 4 warps in N
    const int lrow = lane & 15;
    const uint32_t lcb = (uint32_t)(lane >> 4) * 16;

    // double-buffered fragment sets
    uint32_t ahF[2][4][4], alF[2][4][4], bhF[2][4][2], blF[2][4][2];

#define LDFRAGS(buf, sb, ss) do {                                                            \
    const uint32_t kb_ = (uint32_t)(ss) * 32 + lcb;                                          \
    _Pragma("unroll")                                                                        \
    for (int mi_ = 0; mi_ < 4; mi_++) {                                                      \
        ldsm4(ahF[buf][mi_][0], ahF[buf][mi_][1], ahF[buf][mi_][2], ahF[buf][mi_][3],        \
              (sb) + OAH + (uint32_t)(m0w + 16 * mi_ + lrow) * ROWB + kb_);                  \
        if (NPROD == 3)                                                                      \
            ldsm4(alF[buf][mi_][0], alF[buf][mi_][1], alF[buf][mi_][2], alF[buf][mi_][3],    \
                  (sb) + OAL + (uint32_t)(m0w + 16 * mi_ + lrow) * ROWB + kb_);              \
    }                                                                                        \
    _Pragma("unroll")                                                                        \
    for (int nj_ = 0; nj_ < 2; nj_++) {                                                      \
        uint32_t t0_, t1_, t2_, t3_;                                                         \
        ldsm4(t0_, t1_, t2_, t3_,                                                            \
              (sb) + OBH + (uint32_t)(n0w + 16 * nj_ + lrow) * ROWB + kb_);                  \
        bhF[buf][2*nj_][0] = t0_; bhF[buf][2*nj_][1] = t2_;                                  \
        bhF[buf][2*nj_+1][0] = t1_; bhF[buf][2*nj_+1][1] = t3_;                              \
        ldsm4(t0_, t1_, t2_, t3_,                                                            \
              (sb) + OBL + (uint32_t)(n0w + 16 * nj_ + lrow) * ROWB + kb_);                  \
        blF[buf][2*nj_][0] = t0_; blF[buf][2*nj_][1] = t2_;                                  \
        blF[buf][2*nj_+1][0] = t1_; blF[buf][2*nj_+1][1] = t3_;                              \
    }                                                                                        \
} while (0)

#define DOMMAS(buf) do {                                                                     \
    _Pragma("unroll")                                                                        \
    for (int mi_ = 0; mi_ < 4; mi_++)                                                        \
        _Pragma("unroll")                                                                    \
        for (int ni_ = 0; ni_ < 4; ni_++) mma16816(acc[mi_][ni_], ahF[buf][mi_], bhF[buf][ni_]); \
    _Pragma("unroll")                                                                        \
    for (int mi_ = 0; mi_ < 4; mi_++)                                                        \
        _Pragma("unroll")                                                                    \
        for (int ni_ = 0; ni_ < 4; ni_++) mma16816(acc[mi_][ni_], ahF[buf][mi_], blF[buf][ni_]); \
    if (NPROD == 3) {                                                                        \
        _Pragma("unroll")                                                                    \
        for (int mi_ = 0; mi_ < 4; mi_++)                                                    \
            _Pragma("unroll")                                                                \
            for (int ni_ = 0; ni_ < 4; ni_++) mma16816(acc[mi_][ni_], alF[buf][mi_], bhF[buf][ni_]); \
    }                                                                                        \
} while (0)

    for (int c = 0; c < nk; c++) {
        CP_WAIT0();
        __syncthreads();
        if (c + 1 < nk) { LOAD_STAGE((c + 1) & 1, (c + 1) * 64); CP_COMMIT(); }

        const uint32_t sb = smb + (uint32_t)(c & 1) * STAGE;
        // software pipeline: frags(s+1) issue before MMAs(s)
        LDFRAGS(0, sb, 0);
        LDFRAGS(1, sb, 1);
        DOMMAS(0);
        LDFRAGS(0, sb, 2);
        DOMMAS(1);
        LDFRAGS(1, sb, 3);
        DOMMAS(0);
        DOMMAS(1);
    }

    // ---------------- epilogue ----------------
    const int* maskz = (EPI == 2) ? (mask + z * sC) : nullptr;
    float* Cfz = Cf ? Cf + z * sC : nullptr;
    __half* Chz = Ch ? Ch + z * sC : nullptr;
    __half* Clz = Cl ? Cl + z * sC : nullptr;

#pragma unroll
    for (int mi = 0; mi < 4; mi++) {
#pragma unroll
        for (int ni = 0; ni < 4; ni++) {
            float* a = acc[mi][ni];
            const int r = bm + m0w + 16 * mi + (lane >> 2);
            const int cc = bn + n0w + 8 * ni + (lane & 3) * 2;
            float v0 = a[0], v1 = a[1], v2 = a[2], v3 = a[3];

            if (EPI == 0 || EPI == 1) {
                float2 b = *(const float2*)&bias[cc];
                v0 += b.x; v1 += b.y; v2 += b.x; v3 += b.y;
            }
            if (EPI == 2) {
                int2 mA = *(const int2*)&maskz[(size_t)r * Nt + cc];
                int2 mB = *(const int2*)&maskz[(size_t)(r + 8) * Nt + cc];
                if (mA.x) v0 = -1e18f;
                if (mA.y) v1 = -1e18f;
                if (mB.x) v2 = -1e18f;
                if (mB.y) v3 = -1e18f;
            }
            if (EPI == 4) {
                float2 aA = *(const float2*)&add[(size_t)r * Nt + cc];
                float2 aB = *(const float2*)&add[(size_t)(r + 8) * Nt + cc];
                v0 += aA.x; v1 += aA.y; v2 += aB.x; v3 += aB.y;
            }

            if (EPI == 0) {
                *(uint32_t*)&Chz[(size_t)r * Nt + cc]       = pack_hi2(v0, v1);
                *(uint32_t*)&Clz[(size_t)r * Nt + cc]       = pack_lo2(v0, v1);
                *(uint32_t*)&Chz[(size_t)(r + 8) * Nt + cc] = pack_hi2(v2, v3);
                *(uint32_t*)&Clz[(size_t)(r + 8) * Nt + cc] = pack_lo2(v2, v3);
            } else if (EPI == 5) {
                *(uint32_t*)&Chz[(size_t)r * Nt + cc]       = pack_hi2(v0, v1);
                *(uint32_t*)&Chz[(size_t)(r + 8) * Nt + cc] = pack_hi2(v2, v3);
            } else {
                *(float2*)&Cfz[(size_t)r * Nt + cc]       = make_float2(v0, v1);
                *(float2*)&Cfz[(size_t)(r + 8) * Nt + cc] = make_float2(v2, v3);
            }
        }
    }
}

// ---------------------------------------------------------------------------
// fp32 -> fp16 hi/lo split (elementwise, vectorized)
// ---------------------------------------------------------------------------
__global__ void convsplit_kernel(const float* __restrict__ x,
                                 __half* __restrict__ h,
                                 __half* __restrict__ l, int n)
{
    int i = (blockIdx.x * 256 + threadIdx.x) * 4;
    if (i < n) {
        float4 v = *(const float4*)&x[i];
        *(uint32_t*)&h[i]     = pack_hi2(v.x, v.y);
        *(uint32_t*)&h[i + 2] = pack_hi2(v.z, v.w);
        *(uint32_t*)&l[i]     = pack_lo2(v.x, v.y);
        *(uint32_t*)&l[i + 2] = pack_lo2(v.z, v.w);
    }
}

// 4 weight matrices in one launch (z selects)
__global__ void convsplit4_kernel(
    const float* __restrict__ w0, const float* __restrict__ w1,
    const float* __restrict__ w2, const float* __restrict__ w3,
    __half* __restrict__ h0, __half* __restrict__ l0,
    __half* __restrict__ h1, __half* __restrict__ l1,
    __half* __restrict__ h2, __half* __restrict__ l2,
    __half* __restrict__ h3, __half* __restrict__ l3)
{
    const int zz = blockIdx.z;
    const float* x = (zz == 0) ? w0 : (zz == 1) ? w1 : (zz == 2) ? w2 : w3;
    __half* h = (zz == 0) ? h0 : (zz == 1) ? h1 : (zz == 2) ? h2 : h3;
    __half* l = (zz == 0) ? l0 : (zz == 1) ? l1 : (zz == 2) ? l2 : l3;
    int i = (blockIdx.x * 256 + threadIdx.x) * 4;
    float4 v = *(const float4*)&x[i];
    *(uint32_t*)&h[i]     = pack_hi2(v.x, v.y);
    *(uint32_t*)&h[i + 2] = pack_hi2(v.z, v.w);
    *(uint32_t*)&l[i]     = pack_lo2(v.x, v.y);
    *(uint32_t*)&l[i + 2] = pack_lo2(v.z, v.w);
}

// ---------------------------------------------------------------------------
// v[T,E] fp32 (batched) -> vT hi/lo [E,T] fp16
// ---------------------------------------------------------------------------
__global__ void transconv_kernel(const float* __restrict__ v,
                                 __half* __restrict__ th,
                                 __half* __restrict__ tl)
{
    __shared__ float tile[32][33];
    const long z = blockIdx.z;
    const float* vz = v + z * ((size_t)T_ * E_);
    __half* thz = th + z * ((size_t)T_ * E_);
    __half* tlz = tl + z * ((size_t)T_ * E_);
    const int t0 = blockIdx.x * 32;
    const int e0 = blockIdx.y * 32;
    const int tx = threadIdx.x, ty = threadIdx.y;
#pragma unroll
    for (int i = 0; i < 32; i += 8)
        tile[ty + i][tx] = vz[(size_t)(t0 + ty + i) * E_ + e0 + tx];
    __syncthreads();
#pragma unroll
    for (int i = 0; i < 32; i += 8) {
        float x = tile[tx][ty + i];
        __half hi = __float2half_rn(x);
        size_t o = (size_t)(e0 + ty + i) * T_ + t0 + tx;
        thz[o] = hi;
        tlz[o] = __float2half_rn(x - __half2float(hi));
    }
}

// ---------------------------------------------------------------------------
// reductions
// ---------------------------------------------------------------------------
__device__ __forceinline__ float block_sum_256(float v) {
    __shared__ float sh[8];
    __shared__ float res;
#pragma unroll
    for (int o = 16; o > 0; o >>= 1) v += __shfl_xor_sync(0xffffffffu, v, o);
    const int w = threadIdx.x >> 5;
    if ((threadIdx.x & 31) == 0) sh[w] = v;
    __syncthreads();
    if (threadIdx.x == 0) {
        float t = 0.0f;
#pragma unroll
        for (int i = 0; i < 8; i++) t += sh[i];
        res = t;
    }
    __syncthreads();
    return res;
}
__device__ __forceinline__ float block_max_256(float v) {
    __shared__ float shm[8];
    __shared__ float resm;
#pragma unroll
    for (int o = 16; o > 0; o >>= 1) v = fmaxf(v, __shfl_xor_sync(0xffffffffu, v, o));
    const int w = threadIdx.x >> 5;
    if ((threadIdx.x & 31) == 0) shm[w] = v;
    __syncthreads();
    if (threadIdx.x == 0) {
        float t = shm[0];
#pragma unroll
        for (int i = 1; i < 8; i++) t = fmaxf(t, shm[i]);
        resm = t;
    }
    __syncthreads();
    return resm;
}

// ---------------------------------------------------------------------------
// softmax over T, emits fp16 weights (hi only; PV is 2-product)
// ---------------------------------------------------------------------------
__global__ void __launch_bounds__(256) softmax_split_kernel(
    const float* __restrict__ lg, __half* __restrict__ ph)
{
    const size_t base = (size_t)blockIdx.x * T_;
    const float* p = lg + base;
    const int t = threadIdx.x;
    float vals[8];
    float mx = -__int_as_float(0x7f800000);
#pragma unroll
    for (int i = 0; i < 8; i++) {
        vals[i] = p[t + i * 256];
        mx = fmaxf(mx, vals[i]);
    }
    mx = block_max_256(mx);
    float s = 0.0f;
#pragma unroll
    for (int i = 0; i < 8; i++) {
        vals[i] = __expf(vals[i] - mx);
        s += vals[i];
    }
    s = block_sum_256(s);
    const float inv = 1.0f / s;
#pragma unroll
    for (int i = 0; i < 8; i++)
        ph[base + t + i * 256] = __float2half_rn(vals[i] * inv);
}

// ---------------------------------------------------------------------------
// LayerNorm + residual
// ---------------------------------------------------------------------------
__global__ void __launch_bounds__(256) layernorm_kernel(
    const float* __restrict__ x, const float* __restrict__ enc,
    const float* __restrict__ gamma, const float* __restrict__ beta,
    float* __restrict__ out)
{
    const size_t row = blockIdx.x;
    const float* xr = x + row * E_;
    const float* er = enc + row * E_;
    float* orow = out + row * E_;
    const int t = threadIdx.x;

    const float x0 = xr[t];
    const float x1 = xr[t + 256];
    const float mean = block_sum_256(x0 + x1) * (1.0f / E_);
    const float d0 = x0 - mean;
    const float d1 = x1 - mean;
    const float var = block_sum_256(d0 * d0 + d1 * d1) * (1.0f / E_);
    const float inv = 1.0f / (sqrtf(var) + EPSF);

    orow[t]       = er[t]       + gamma[t]       * d0 * inv + beta[t];
    orow[t + 256] = er[t + 256] + gamma[t + 256] * d1 * inv + beta[t + 256];
}

// ---------------------------------------------------------------------------
// launch
// ---------------------------------------------------------------------------
extern "C" void kernel_launch(void* const* d_in, const int* in_sizes, int n_in,
                              void* d_out, int out_size)
{
    const float* enc  = (const float*)d_in[0];
    const float* emo  = (const float*)d_in[1];
    const int*   mask = (const int*)d_in[2];
    const float* Wq   = (const float*)d_in[3];
    const float* bq   = (const float*)d_in[4];
    const float* Wk   = (const float*)d_in[5];
    const float* bk   = (const float*)d_in[6];
    const float* Wv   = (const float*)d_in[7];
    const float* bv   = (const float*)d_in[8];
    const float* Wo   = (const float*)d_in[9];
    const float* gamma = (const float*)d_in[10];
    const float* beta  = (const float*)d_in[11];
    float* out = (float*)d_out;

    __half *encH,*encL,*emoH,*emoL,*WqH,*WqL,*WkH,*WkL,*WvH,*WvL,*WoH,*WoL;
    __half *qH,*qL,*kH,*kL,*vTH,*vTL,*pH,*ctxH;
    float *v, *lg, *tmp;
    cudaGetSymbolAddress((void**)&encH, g_encH); cudaGetSymbolAddress((void**)&encL, g_encL);
    cudaGetSymbolAddress((void**)&emoH, g_emoH); cudaGetSymbolAddress((void**)&emoL, g_emoL);
    cudaGetSymbolAddress((void**)&WqH, g_WqH); cudaGetSymbolAddress((void**)&WqL, g_WqL);
    cudaGetSymbolAddress((void**)&WkH, g_WkH); cudaGetSymbolAddress((void**)&WkL, g_WkL);
    cudaGetSymbolAddress((void**)&WvH, g_WvH); cudaGetSymbolAddress((void**)&WvL, g_WvL);
    cudaGetSymbolAddress((void**)&WoH, g_WoH); cudaGetSymbolAddress((void**)&WoL, g_WoL);
    cudaGetSymbolAddress((void**)&qH, g_qH); cudaGetSymbolAddress((void**)&qL, g_qL);
    cudaGetSymbolAddress((void**)&kH, g_kH); cudaGetSymbolAddress((void**)&kL, g_kL);
    cudaGetSymbolAddress((void**)&vTH, g_vTH); cudaGetSymbolAddress((void**)&vTL, g_vTL);
    cudaGetSymbolAddress((void**)&pH, g_pH);
    cudaGetSymbolAddress((void**)&ctxH, g_ctxH);
    cudaGetSymbolAddress((void**)&v, g_v);
    cudaGetSymbolAddress((void**)&lg, g_logits);
    cudaGetSymbolAddress((void**)&tmp, g_tmp);

    const int SMEM3 = 2 * 73728;    // 147456 (NPROD=3)
    const int SMEM2 = 2 * 55296;    // 110592 (NPROD=2)
    cudaFuncSetAttribute(gemm_mma<0,3>, cudaFuncAttributeMaxDynamicSharedMemorySize, SMEM3);
    cudaFuncSetAttribute(gemm_mma<2,3>, cudaFuncAttributeMaxDynamicSharedMemorySize, SMEM3);
    cudaFuncSetAttribute(gemm_mma<1,2>, cudaFuncAttributeMaxDynamicSharedMemorySize, SMEM2);
    cudaFuncSetAttribute(gemm_mma<5,2>, cudaFuncAttributeMaxDynamicSharedMemorySize, SMEM2);
    cudaFuncSetAttribute(gemm_mma<4,2>, cudaFuncAttributeMaxDynamicSharedMemorySize, SMEM2);

    // 1-2) input splits
    convsplit_kernel<<<NSE / 1024, 256>>>(enc, encH, encL, NSE);
    convsplit_kernel<<<NSE / 1024, 256>>>(emo, emoH, emoL, NSE);
    // 3) all 4 weight splits in one launch
    convsplit4_kernel<<<dim3((E_*E_) / 1024, 1, 4), 256>>>(
        Wq, Wk, Wv, Wo, WqH, WqL, WkH, WkL, WvH, WvL, WoH, WoL);

    // 4-5) Q and K projections (3-product: feed logits, error-critical)
    const dim3 gp(E_ / 128, (B_ * S_) / 128, 1);
    gemm_mma<0,3><<<gp, 256, SMEM3>>>(encH, encL, WqH, WqL, E_, E_, 0, 0, 0,
                                      bq, nullptr, nullptr, nullptr, qH, qL);
    gemm_mma<0,3><<<gp, 256, SMEM3>>>(emoH, emoL, WkH, WkL, E_, E_, 0, 0, 0,
                                      bk, nullptr, nullptr, nullptr, kH, kL);

    // 6) logits = q k^T + mask (3-product; profiled launch: -s 5 -c 1)
    const dim3 gl(T_ / 128, S_ / 128, B_);
    gemm_mma<2,3><<<gl, 256, SMEM3>>>(qH, qL, kH, kL, E_, T_,
                                      (long)S_ * E_, (long)T_ * E_, (long)S_ * T_,
                                      nullptr, mask, nullptr, lg, nullptr, nullptr);

    // 7) V projection (2-product: diluted path)
    gemm_mma<1,2><<<gp, 256, SMEM2>>>(emoH, nullptr, WvH, WvL, E_, E_, 0, 0, 0,
                                      bv, nullptr, nullptr, v, nullptr, nullptr);

    // 8) v -> vT hi/lo
    transconv_kernel<<<dim3(T_ / 32, E_ / 32, B_), dim3(32, 8)>>>(v, vTH, vTL);

    // 9) softmax -> P hi (fp16)
    softmax_split_kernel<<<B_ * S_, 256>>>(lg, pH);

    // 10) ctx = P @ v (2-product; A = P hi only), ctx stored hi only
    const dim3 gc(E_ / 128, S_ / 128, B_);
    gemm_mma<5,2><<<gc, 256, SMEM2>>>(pH, nullptr, vTH, vTL, T_, E_,
                                      (long)S_ * T_, (long)T_ * E_, (long)S_ * E_,
                                      nullptr, nullptr, nullptr, nullptr, ctxH, nullptr);

    // 11) tmp = ctx @ Wo^T + enc (2-product)
    const dim3 go(E_ / 128, (B_ * S_) / 128, 1);
    gemm_mma<4,2><<<go, 256, SMEM2>>>(ctxH, nullptr, WoH, WoL, E_, E_, 0, 0, 0,
                                      nullptr, nullptr, enc, tmp, nullptr, nullptr);

    // 12) out = enc + LN(tmp)
    layernorm_kernel<<<B_ * S_, 256>>>(tmp, enc, gamma, beta, out);
}

// round 15
// speedup vs baseline: 1.0705x; 1.0705x over previous
#include <cuda_runtime.h>
#include <cuda_fp16.h>
#include <cstdint>

#define EPSF 1e-6f

constexpr int B_ = 8;
constexpr int S_ = 2048;
constexpr int T_ = 2048;
constexpr int E_ = 512;

constexpr int NSE = B_ * S_ * E_;               // 8388608
constexpr size_t NST = (size_t)B_ * S_ * T_;    // 33554432

// ---------------- scratch (device globals) ----------------
__device__ __half g_encH[NSE], g_encL[NSE];
__device__ __half g_emoH[NSE], g_emoL[NSE];
__device__ __half g_WqH[E_*E_], g_WqL[E_*E_];
__device__ __half g_WkH[E_*E_], g_WkL[E_*E_];
__device__ __half g_WvH[E_*E_], g_WvL[E_*E_];
__device__ __half g_WoH[E_*E_], g_WoL[E_*E_];
__device__ __half g_qH[NSE], g_qL[NSE];
__device__ __half g_kH[NSE], g_kL[NSE];
__device__ float  g_v[NSE];
__device__ __half g_vTH[NSE], g_vTL[NSE];
__device__ float  g_logits[NST];
__device__ __half g_pH[NST];
__device__ __half g_ctxH[NSE];
__device__ float  g_tmp[NSE];

// ---------------- helpers ----------------
__device__ __forceinline__ uint32_t smem_u32(const void* p) {
    uint32_t a;
    asm("{ .reg .u64 t; cvta.to.shared.u64 t, %1; cvt.u32.u64 %0, t; }" : "=r"(a) : "l"(p));
    return a;
}
#define CP16(dst, src) asm volatile("cp.async.cg.shared.global [%0], [%1], 16;" :: "r"(dst), "l"(src))
#define CP_COMMIT()    asm volatile("cp.async.commit_group;")
#define CP_WAIT0()     asm volatile("cp.async.wait_group 0;")

__device__ __forceinline__ void ldsm4(uint32_t& r0, uint32_t& r1, uint32_t& r2, uint32_t& r3, uint32_t a) {
    asm volatile("ldmatrix.sync.aligned.m8n8.x4.shared.b16 {%0,%1,%2,%3}, [%4];"
                 : "=r"(r0), "=r"(r1), "=r"(r2), "=r"(r3) : "r"(a));
}
__device__ __forceinline__ void mma16816(float* c, const uint32_t* a, const uint32_t* b) {
    asm volatile("mma.sync.aligned.m16n8k16.row.col.f32.f16.f16.f32 "
                 "{%0,%1,%2,%3}, {%4,%5,%6,%7}, {%8,%9}, {%0,%1,%2,%3};"
                 : "+f"(c[0]), "+f"(c[1]), "+f"(c[2]), "+f"(c[3])
                 : "r"(a[0]), "r"(a[1]), "r"(a[2]), "r"(a[3]), "r"(b[0]), "r"(b[1]));
}
__device__ __forceinline__ uint32_t pack_hi2(float x, float y) {
    unsigned short hx = __half_as_ushort(__float2half_rn(x));
    unsigned short hy = __half_as_ushort(__float2half_rn(y));
    return (uint32_t)hx | ((uint32_t)hy << 16);
}
__device__ __forceinline__ uint32_t pack_lo2(float x, float y) {
    float hx = __half2float(__float2half_rn(x));
    float hy = __half2float(__float2half_rn(y));
    unsigned short lx = __half_as_ushort(__float2half_rn(x - hx));
    unsigned short ly = __half_as_ushort(__float2half_rn(y - hy));
    return (uint32_t)lx | ((uint32_t)ly << 16);
}

// ---------------------------------------------------------------------------
// fp16-split GEMM via mma.sync, NT form: C[m,n] = sum_k A[m,k]*B[n,k].
// Block tile 128x256, BK=64, 512 threads (16 warps, warp tile 64x32),
// 2-stage cp.async. NPROD=3: AhBh+AhBl+AlBh (near-fp32).
// NPROD=2: AhBh+AhBl (A-lo never loaded; err ~2^-12, used on diluted paths).
// EPI: 0 bias+split(hi,lo), 1 bias+f32, 2 mask+f32, 4 add+f32, 5 split hi-only
// ---------------------------------------------------------------------------
template <int EPI, int NPROD>
__global__ void __launch_bounds__(512, 1) gemm_mma(
    const __half* __restrict__ Ah, const __half* __restrict__ Al,
    const __half* __restrict__ Bh, const __half* __restrict__ Bl,
    int K, int Nt,
    long sA, long sB, long sC,
    const float* __restrict__ bias,
    const int* __restrict__ mask,
    const float* __restrict__ add,
    float* __restrict__ Cf,
    __half* __restrict__ Ch, __half* __restrict__ Cl)
{
    extern __shared__ __align__(16) char dsm[];
    constexpr uint32_t ROWB = 144;                      // 64 fp16 (128B) + 16B pad
    constexpr uint32_t OAH = 0;                         // A-hi: 128*144 = 18432
    constexpr uint32_t OAL = 18432;                     // A-lo (NPROD=3 only)
    constexpr uint32_t OBH = (NPROD == 3) ? 36864u : 18432u;
    constexpr uint32_t OBL = OBH + 36864;               // B tiles: 256*144
    constexpr uint32_t STAGE = OBL + 36864;             // 110592 or 92160

    const uint32_t smb = smem_u32(dsm);
    const int tid = threadIdx.x;
    const int lane = tid & 31;
    const int wid = tid >> 5;

    const int bm = blockIdx.y * 128;
    const int bn = blockIdx.x * 256;
    const long z = blockIdx.z;

    const __half* bAh = Ah + z * sA;
    const __half* bAl = (NPROD == 3) ? (Al + z * sA) : nullptr;
    const __half* bBh = Bh + z * sB;
    const __half* bBl = Bl + z * sB;

    // loader: per stage A = 1024 16B-chunks per tensor (2/thr), B = 2048 (4/thr)
#define LOAD_STAGE(stg, k0) do {                                                             \
    uint32_t sb_ = smb + (uint32_t)(stg) * STAGE;                                            \
    _Pragma("unroll")                                                                        \
    for (int i_ = 0; i_ < 2; i_++) {                                                         \
        int id_ = tid + i_ * 512, rA_ = id_ >> 3, sA_ = id_ & 7;                             \
        CP16(sb_ + OAH + rA_ * ROWB + sA_ * 16, bAh + (size_t)(bm + rA_) * K + (k0) + sA_ * 8);\
        if (NPROD == 3)                                                                      \
            CP16(sb_ + OAL + rA_ * ROWB + sA_ * 16, bAl + (size_t)(bm + rA_) * K + (k0) + sA_ * 8);\
    }                                                                                        \
    _Pragma("unroll")                                                                        \
    for (int i_ = 0; i_ < 4; i_++) {                                                         \
        int id_ = tid + i_ * 512, rB_ = id_ >> 3, sB_ = id_ & 7;                             \
        CP16(sb_ + OBH + rB_ * ROWB + sB_ * 16, bBh + (size_t)(bn + rB_) * K + (k0) + sB_ * 8);\
        CP16(sb_ + OBL + rB_ * ROWB + sB_ * 16, bBl + (size_t)(bn + rB_) * K + (k0) + sB_ * 8);\
    }                                                                                        \
} while (0)

    float acc[4][4][4];
#pragma unroll
    for (int i = 0; i < 4; i++)
#pragma unroll
        for (int j = 0; j < 4; j++)
#pragma unroll
            for (int t = 0; t < 4; t++) acc[i][j][t] = 0.0f;

    const int nk = K >> 6;
    LOAD_STAGE(0, 0);
    CP_COMMIT();

    const int m0w = (wid & 1) * 64;      // 2 warps in M
    const int n0w = (wid >> 1) * 32;     // 8 warps in N
    const int lrow = lane & 15;
    const uint32_t lcb = (uint32_t)(lane >> 4) * 16;

    for (int c = 0; c < nk; c++) {
        CP_WAIT0();
        __syncthreads();
        if (c + 1 < nk) { LOAD_STAGE((c + 1) & 1, (c + 1) * 64); CP_COMMIT(); }

        const uint32_t sb = smb + (uint32_t)(c & 1) * STAGE;
#pragma unroll
        for (int s = 0; s < 4; s++) {
            const uint32_t kb = (uint32_t)s * 32 + lcb;

            if (NPROD == 3) {
                uint32_t ah[4][4], al[4][4];
#pragma unroll
                for (int mi = 0; mi < 4; mi++) {
                    ldsm4(ah[mi][0], ah[mi][1], ah[mi][2], ah[mi][3],
                          sb + OAH + (uint32_t)(m0w + 16 * mi + lrow) * ROWB + kb);
                    ldsm4(al[mi][0], al[mi][1], al[mi][2], al[mi][3],
                          sb + OAL + (uint32_t)(m0w + 16 * mi + lrow) * ROWB + kb);
                }
#pragma unroll
                for (int nj = 0; nj < 2; nj++) {
                    uint32_t t0, t1, t2, t3;
                    uint32_t b0[2], b1[2];
                    ldsm4(t0, t1, t2, t3,
                          sb + OBH + (uint32_t)(n0w + 16 * nj + lrow) * ROWB + kb);
                    b0[0] = t0; b0[1] = t2; b1[0] = t1; b1[1] = t3;
#pragma unroll
                    for (int mi = 0; mi < 4; mi++) mma16816(acc[mi][2*nj],   ah[mi], b0);
#pragma unroll
                    for (int mi = 0; mi < 4; mi++) mma16816(acc[mi][2*nj+1], ah[mi], b1);
#pragma unroll
                    for (int mi = 0; mi < 4; mi++) mma16816(acc[mi][2*nj],   al[mi], b0);
#pragma unroll
                    for (int mi = 0; mi < 4; mi++) mma16816(acc[mi][2*nj+1], al[mi], b1);
                    ldsm4(t0, t1, t2, t3,
                          sb + OBL + (uint32_t)(n0w + 16 * nj + lrow) * ROWB + kb);
                    b0[0] = t0; b0[1] = t2; b1[0] = t1; b1[1] = t3;
#pragma unroll
                    for (int mi = 0; mi < 4; mi++) mma16816(acc[mi][2*nj],   ah[mi], b0);
#pragma unroll
                    for (int mi = 0; mi < 4; mi++) mma16816(acc[mi][2*nj+1], ah[mi], b1);
                }
            } else {
                uint32_t ah[4][4];
#pragma unroll
                for (int mi = 0; mi < 4; mi++)
                    ldsm4(ah[mi][0], ah[mi][1], ah[mi][2], ah[mi][3],
                          sb + OAH + (uint32_t)(m0w + 16 * mi + lrow) * ROWB + kb);
#pragma unroll
                for (int nj = 0; nj < 2; nj++) {
                    uint32_t t0, t1, t2, t3;
                    uint32_t b0[2], b1[2];
                    ldsm4(t0, t1, t2, t3,
                          sb + OBH + (uint32_t)(n0w + 16 * nj + lrow) * ROWB + kb);
                    b0[0] = t0; b0[1] = t2; b1[0] = t1; b1[1] = t3;
#pragma unroll
                    for (int mi = 0; mi < 4; mi++) mma16816(acc[mi][2*nj],   ah[mi], b0);
#pragma unroll
                    for (int mi = 0; mi < 4; mi++) mma16816(acc[mi][2*nj+1], ah[mi], b1);
                    ldsm4(t0, t1, t2, t3,
                          sb + OBL + (uint32_t)(n0w + 16 * nj + lrow) * ROWB + kb);
                    b0[0] = t0; b0[1] = t2; b1[0] = t1; b1[1] = t3;
#pragma unroll
                    for (int mi = 0; mi < 4; mi++) mma16816(acc[mi][2*nj],   ah[mi], b0);
#pragma unroll
                    for (int mi = 0; mi < 4; mi++) mma16816(acc[mi][2*nj+1], ah[mi], b1);
                }
            }
        }
    }

    // ---------------- epilogue ----------------
    const int* maskz = (EPI == 2) ? (mask + z * sC) : nullptr;
    float* Cfz = Cf ? Cf + z * sC : nullptr;
    __half* Chz = Ch ? Ch + z * sC : nullptr;
    __half* Clz = Cl ? Cl + z * sC : nullptr;

#pragma unroll
    for (int mi = 0; mi < 4; mi++) {
#pragma unroll
        for (int ni = 0; ni < 4; ni++) {
            float* a = acc[mi][ni];
            const int r = bm + m0w + 16 * mi + (lane >> 2);
            const int cc = bn + n0w + 8 * ni + (lane & 3) * 2;
            float v0 = a[0], v1 = a[1], v2 = a[2], v3 = a[3];

            if (EPI == 0 || EPI == 1) {
                float2 b = *(const float2*)&bias[cc];
                v0 += b.x; v1 += b.y; v2 += b.x; v3 += b.y;
            }
            if (EPI == 2) {
                int2 mA = *(const int2*)&maskz[(size_t)r * Nt + cc];
                int2 mB = *(const int2*)&maskz[(size_t)(r + 8) * Nt + cc];
                if (mA.x) v0 = -1e18f;
                if (mA.y) v1 = -1e18f;
                if (mB.x) v2 = -1e18f;
                if (mB.y) v3 = -1e18f;
            }
            if (EPI == 4) {
                float2 aA = *(const float2*)&add[(size_t)r * Nt + cc];
                float2 aB = *(const float2*)&add[(size_t)(r + 8) * Nt + cc];
                v0 += aA.x; v1 += aA.y; v2 += aB.x; v3 += aB.y;
            }

            if (EPI == 0) {
                *(uint32_t*)&Chz[(size_t)r * Nt + cc]       = pack_hi2(v0, v1);
                *(uint32_t*)&Clz[(size_t)r * Nt + cc]       = pack_lo2(v0, v1);
                *(uint32_t*)&Chz[(size_t)(r + 8) * Nt + cc] = pack_hi2(v2, v3);
                *(uint32_t*)&Clz[(size_t)(r + 8) * Nt + cc] = pack_lo2(v2, v3);
            } else if (EPI == 5) {
                *(uint32_t*)&Chz[(size_t)r * Nt + cc]       = pack_hi2(v0, v1);
                *(uint32_t*)&Chz[(size_t)(r + 8) * Nt + cc] = pack_hi2(v2, v3);
            } else {
                *(float2*)&Cfz[(size_t)r * Nt + cc]       = make_float2(v0, v1);
                *(float2*)&Cfz[(size_t)(r + 8) * Nt + cc] = make_float2(v2, v3);
            }
        }
    }
}

// ---------------------------------------------------------------------------
// fp32 -> fp16 hi/lo split; z selects (enc, emo) so one launch covers both
// ---------------------------------------------------------------------------
__global__ void convsplit2_kernel(
    const float* __restrict__ x0, __half* __restrict__ h0, __half* __restrict__ l0,
    const float* __restrict__ x1, __half* __restrict__ h1, __half* __restrict__ l1)
{
    const float* x = (blockIdx.z == 0) ? x0 : x1;
    __half* h = (blockIdx.z == 0) ? h0 : h1;
    __half* l = (blockIdx.z == 0) ? l0 : l1;
    int i = (blockIdx.x * 256 + threadIdx.x) * 4;
    float4 v = *(const float4*)&x[i];
    *(uint32_t*)&h[i]     = pack_hi2(v.x, v.y);
    *(uint32_t*)&h[i + 2] = pack_hi2(v.z, v.w);
    *(uint32_t*)&l[i]     = pack_lo2(v.x, v.y);
    *(uint32_t*)&l[i + 2] = pack_lo2(v.z, v.w);
}

// 4 weight matrices in one launch (z selects)
__global__ void convsplit4_kernel(
    const float* __restrict__ w0, const float* __restrict__ w1,
    const float* __restrict__ w2, const float* __restrict__ w3,
    __half* __restrict__ h0, __half* __restrict__ l0,
    __half* __restrict__ h1, __half* __restrict__ l1,
    __half* __restrict__ h2, __half* __restrict__ l2,
    __half* __restrict__ h3, __half* __restrict__ l3)
{
    const int zz = blockIdx.z;
    const float* x = (zz == 0) ? w0 : (zz == 1) ? w1 : (zz == 2) ? w2 : w3;
    __half* h = (zz == 0) ? h0 : (zz == 1) ? h1 : (zz == 2) ? h2 : h3;
    __half* l = (zz == 0) ? l0 : (zz == 1) ? l1 : (zz == 2) ? l2 : l3;
    int i = (blockIdx.x * 256 + threadIdx.x) * 4;
    float4 v = *(const float4*)&x[i];
    *(uint32_t*)&h[i]     = pack_hi2(v.x, v.y);
    *(uint32_t*)&h[i + 2] = pack_hi2(v.z, v.w);
    *(uint32_t*)&l[i]     = pack_lo2(v.x, v.y);
    *(uint32_t*)&l[i + 2] = pack_lo2(v.z, v.w);
}

// ---------------------------------------------------------------------------
// v[T,E] fp32 (batched) -> vT hi/lo [E,T] fp16
// ---------------------------------------------------------------------------
__global__ void transconv_kernel(const float* __restrict__ v,
                                 __half* __restrict__ th,
                                 __half* __restrict__ tl)
{
    __shared__ float tile[32][33];
    const long z = blockIdx.z;
    const float* vz = v + z * ((size_t)T_ * E_);
    __half* thz = th + z * ((size_t)T_ * E_);
    __half* tlz = tl + z * ((size_t)T_ * E_);
    const int t0 = blockIdx.x * 32;
    const int e0 = blockIdx.y * 32;
    const int tx = threadIdx.x, ty = threadIdx.y;
#pragma unroll
    for (int i = 0; i < 32; i += 8)
        tile[ty + i][tx] = vz[(size_t)(t0 + ty + i) * E_ + e0 + tx];
    __syncthreads();
#pragma unroll
    for (int i = 0; i < 32; i += 8) {
        float x = tile[tx][ty + i];
        __half hi = __float2half_rn(x);
        size_t o = (size_t)(e0 + ty + i) * T_ + t0 + tx;
        thz[o] = hi;
        tlz[o] = __float2half_rn(x - __half2float(hi));
    }
}

// ---------------------------------------------------------------------------
// reductions
// ---------------------------------------------------------------------------
__device__ __forceinline__ float block_sum_256(float v) {
    __shared__ float sh[8];
    __shared__ float res;
#pragma unroll
    for (int o = 16; o > 0; o >>= 1) v += __shfl_xor_sync(0xffffffffu, v, o);
    const int w = threadIdx.x >> 5;
    if ((threadIdx.x & 31) == 0) sh[w] = v;
    __syncthreads();
    if (threadIdx.x == 0) {
        float t = 0.0f;
#pragma unroll
        for (int i = 0; i < 8; i++) t += sh[i];
        res = t;
    }
    __syncthreads();
    return res;
}
__device__ __forceinline__ float block_max_256(float v) {
    __shared__ float shm[8];
    __shared__ float resm;
#pragma unroll
    for (int o = 16; o > 0; o >>= 1) v = fmaxf(v, __shfl_xor_sync(0xffffffffu, v, o));
    const int w = threadIdx.x >> 5;
    if ((threadIdx.x & 31) == 0) shm[w] = v;
    __syncthreads();
    if (threadIdx.x == 0) {
        float t = shm[0];
#pragma unroll
        for (int i = 1; i < 8; i++) t = fmaxf(t, shm[i]);
        resm = t;
    }
    __syncthreads();
    return resm;
}

// ---------------------------------------------------------------------------
// softmax over T, emits fp16 weights (hi only; PV is 2-product)
// ---------------------------------------------------------------------------
__global__ void __launch_bounds__(256) softmax_split_kernel(
    const float* __restrict__ lg, __half* __restrict__ ph)
{
    const size_t base = (size_t)blockIdx.x * T_;
    const float* p = lg + base;
    const int t = threadIdx.x;
    float vals[8];
    float mx = -__int_as_float(0x7f800000);
#pragma unroll
    for (int i = 0; i < 8; i++) {
        vals[i] = p[t + i * 256];
        mx = fmaxf(mx, vals[i]);
    }
    mx = block_max_256(mx);
    float s = 0.0f;
#pragma unroll
    for (int i = 0; i < 8; i++) {
        vals[i] = __expf(vals[i] - mx);
        s += vals[i];
    }
    s = block_sum_256(s);
    const float inv = 1.0f / s;
#pragma unroll
    for (int i = 0; i < 8; i++)
        ph[base + t + i * 256] = __float2half_rn(vals[i] * inv);
}

// ---------------------------------------------------------------------------
// LayerNorm + residual
// ---------------------------------------------------------------------------
__global__ void __launch_bounds__(256) layernorm_kernel(
    const float* __restrict__ x, const float* __restrict__ enc,
    const float* __restrict__ gamma, const float* __restrict__ beta,
    float* __restrict__ out)
{
    const size_t row = blockIdx.x;
    const float* xr = x + row * E_;
    const float* er = enc + row * E_;
    float* orow = out + row * E_;
    const int t = threadIdx.x;

    const float x0 = xr[t];
    const float x1 = xr[t + 256];
    const float mean = block_sum_256(x0 + x1) * (1.0f / E_);
    const float d0 = x0 - mean;
    const float d1 = x1 - mean;
    const float var = block_sum_256(d0 * d0 + d1 * d1) * (1.0f / E_);
    const float inv = 1.0f / (sqrtf(var) + EPSF);

    orow[t]       = er[t]       + gamma[t]       * d0 * inv + beta[t];
    orow[t + 256] = er[t + 256] + gamma[t + 256] * d1 * inv + beta[t + 256];
}

// ---------------------------------------------------------------------------
// launch
// ---------------------------------------------------------------------------
extern "C" void kernel_launch(void* const* d_in, const int* in_sizes, int n_in,
                              void* d_out, int out_size)
{
    const float* enc  = (const float*)d_in[0];
    const float* emo  = (const float*)d_in[1];
    const int*   mask = (const int*)d_in[2];
    const float* Wq   = (const float*)d_in[3];
    const float* bq   = (const float*)d_in[4];
    const float* Wk   = (const float*)d_in[5];
    const float* bk   = (const float*)d_in[6];
    const float* Wv   = (const float*)d_in[7];
    const float* bv   = (const float*)d_in[8];
    const float* Wo   = (const float*)d_in[9];
    const float* gamma = (const float*)d_in[10];
    const float* beta  = (const float*)d_in[11];
    float* out = (float*)d_out;

    __half *encH,*encL,*emoH,*emoL,*WqH,*WqL,*WkH,*WkL,*WvH,*WvL,*WoH,*WoL;
    __half *qH,*qL,*kH,*kL,*vTH,*vTL,*pH,*ctxH;
    float *v, *lg, *tmp;
    cudaGetSymbolAddress((void**)&encH, g_encH); cudaGetSymbolAddress((void**)&encL, g_encL);
    cudaGetSymbolAddress((void**)&emoH, g_emoH); cudaGetSymbolAddress((void**)&emoL, g_emoL);
    cudaGetSymbolAddress((void**)&WqH, g_WqH); cudaGetSymbolAddress((void**)&WqL, g_WqL);
    cudaGetSymbolAddress((void**)&WkH, g_WkH); cudaGetSymbolAddress((void**)&WkL, g_WkL);
    cudaGetSymbolAddress((void**)&WvH, g_WvH); cudaGetSymbolAddress((void**)&WvL, g_WvL);
    cudaGetSymbolAddress((void**)&WoH, g_WoH); cudaGetSymbolAddress((void**)&WoL, g_WoL);
    cudaGetSymbolAddress((void**)&qH, g_qH); cudaGetSymbolAddress((void**)&qL, g_qL);
    cudaGetSymbolAddress((void**)&kH, g_kH); cudaGetSymbolAddress((void**)&kL, g_kL);
    cudaGetSymbolAddress((void**)&vTH, g_vTH); cudaGetSymbolAddress((void**)&vTL, g_vTL);
    cudaGetSymbolAddress((void**)&pH, g_pH);
    cudaGetSymbolAddress((void**)&ctxH, g_ctxH);
    cudaGetSymbolAddress((void**)&v, g_v);
    cudaGetSymbolAddress((void**)&lg, g_logits);
    cudaGetSymbolAddress((void**)&tmp, g_tmp);

    const int SMEM3 = 2 * 110592;   // 221184 (NPROD=3)
    const int SMEM2 = 2 * 92160;    // 184320 (NPROD=2)
    cudaFuncSetAttribute(gemm_mma<0,3>, cudaFuncAttributeMaxDynamicSharedMemorySize, SMEM3);
    cudaFuncSetAttribute(gemm_mma<2,3>, cudaFuncAttributeMaxDynamicSharedMemorySize, SMEM3);
    cudaFuncSetAttribute(gemm_mma<1,2>, cudaFuncAttributeMaxDynamicSharedMemorySize, SMEM2);
    cudaFuncSetAttribute(gemm_mma<5,2>, cudaFuncAttributeMaxDynamicSharedMemorySize, SMEM2);
    cudaFuncSetAttribute(gemm_mma<4,2>, cudaFuncAttributeMaxDynamicSharedMemorySize, SMEM2);

    // 1) input splits (enc + emo in one launch)
    convsplit2_kernel<<<dim3(NSE / 1024, 1, 2), 256>>>(enc, encH, encL, emo, emoH, emoL);
    // 2) all 4 weight splits in one launch
    convsplit4_kernel<<<dim3((E_*E_) / 1024, 1, 4), 256>>>(
        Wq, Wk, Wv, Wo, WqH, WqL, WkH, WkL, WvH, WvL, WoH, WoL);

    // 3-4) Q and K projections (3-product: feed logits, error-critical)
    const dim3 gp(E_ / 256, (B_ * S_) / 128, 1);
    gemm_mma<0,3><<<gp, 512, SMEM3>>>(encH, encL, WqH, WqL, E_, E_, 0, 0, 0,
                                      bq, nullptr, nullptr, nullptr, qH, qL);
    gemm_mma<0,3><<<gp, 512, SMEM3>>>(emoH, emoL, WkH, WkL, E_, E_, 0, 0, 0,
                                      bk, nullptr, nullptr, nullptr, kH, kL);

    // 5) logits = q k^T + mask (3-product) — profiled slot
    const dim3 gl(T_ / 256, S_ / 128, B_);
    gemm_mma<2,3><<<gl, 512, SMEM3>>>(qH, qL, kH, kL, E_, T_,
                                      (long)S_ * E_, (long)T_ * E_, (long)S_ * T_,
                                      nullptr, mask, nullptr, lg, nullptr, nullptr);

    // 6) V projection (2-product: diluted path)
    gemm_mma<1,2><<<gp, 512, SMEM2>>>(emoH, nullptr, WvH, WvL, E_, E_, 0, 0, 0,
                                      bv, nullptr, nullptr, v, nullptr, nullptr);

    // 7) v -> vT hi/lo
    transconv_kernel<<<dim3(T_ / 32, E_ / 32, B_), dim3(32, 8)>>>(v, vTH, vTL);

    // 8) softmax -> P hi (fp16)
    softmax_split_kernel<<<B_ * S_, 256>>>(lg, pH);

    // 9) ctx = P @ v (2-product; A = P hi only), ctx stored hi only
    const dim3 gc(E_ / 256, S_ / 128, B_);
    gemm_mma<5,2><<<gc, 512, SMEM2>>>(pH, nullptr, vTH, vTL, T_, E_,
                                      (long)S_ * T_, (long)T_ * E_, (long)S_ * E_,
                                      nullptr, nullptr, nullptr, nullptr, ctxH, nullptr);

    // 10) tmp = ctx @ Wo^T + enc (2-product)
    const dim3 go(E_ / 256, (B_ * S_) / 128, 1);
    gemm_mma<4,2><<<go, 512, SMEM2>>>(ctxH, nullptr, WoH, WoL, E_, E_, 0, 0, 0,
                                      nullptr, nullptr, enc, tmp, nullptr, nullptr);

    // 11) out = enc + LN(tmp)
    layernorm_kernel<<<B_ * S_, 256>>>(tmp, enc, gamma, beta, out);
}

// round 16
// speedup vs baseline: 1.0920x; 1.0201x over previous
#include <cuda_runtime.h>
#include <cuda_fp16.h>
#include <cstdint>

#define EPSF 1e-6f

constexpr int B_ = 8;
constexpr int S_ = 2048;
constexpr int T_ = 2048;
constexpr int E_ = 512;

constexpr int NSE = B_ * S_ * E_;               // 8388608
constexpr size_t NST = (size_t)B_ * S_ * T_;    // 33554432

// ---------------- scratch (device globals) ----------------
__device__ __half g_encH[NSE], g_encL[NSE];
__device__ __half g_emoH[NSE], g_emoL[NSE];
__device__ float  g_N[E_*E_], g_W2[E_*E_];
__device__ __half g_NH[E_*E_], g_NL[E_*E_];
__device__ __half g_W2H[E_*E_], g_W2L[E_*E_];
__device__ float  g_w1[E_], g_wv2[E_], g_b2[E_], g_c0[1];
__device__ float  g_cs[B_*S_], g_ct[B_*T_];
__device__ __half g_UH[NSE], g_UL[NSE];
__device__ __half g_eTH[NSE], g_eTL[NSE];
__device__ float  g_logits[NST];
__device__ __half g_pH[NST];
__device__ __half g_YH[NSE];
__device__ float  g_tmp[NSE];

// ---------------- helpers ----------------
__device__ __forceinline__ uint32_t smem_u32(const void* p) {
    uint32_t a;
    asm("{ .reg .u64 t; cvta.to.shared.u64 t, %1; cvt.u32.u64 %0, t; }" : "=r"(a) : "l"(p));
    return a;
}
#define CP16(dst, src) asm volatile("cp.async.cg.shared.global [%0], [%1], 16;" :: "r"(dst), "l"(src))
#define CP_COMMIT()    asm volatile("cp.async.commit_group;")
#define CP_WAIT0()     asm volatile("cp.async.wait_group 0;")

__device__ __forceinline__ void ldsm4(uint32_t& r0, uint32_t& r1, uint32_t& r2, uint32_t& r3, uint32_t a) {
    asm volatile("ldmatrix.sync.aligned.m8n8.x4.shared.b16 {%0,%1,%2,%3}, [%4];"
                 : "=r"(r0), "=r"(r1), "=r"(r2), "=r"(r3) : "r"(a));
}
__device__ __forceinline__ void mma16816(float* c, const uint32_t* a, const uint32_t* b) {
    asm volatile("mma.sync.aligned.m16n8k16.row.col.f32.f16.f16.f32 "
                 "{%0,%1,%2,%3}, {%4,%5,%6,%7}, {%8,%9}, {%0,%1,%2,%3};"
                 : "+f"(c[0]), "+f"(c[1]), "+f"(c[2]), "+f"(c[3])
                 : "r"(a[0]), "r"(a[1]), "r"(a[2]), "r"(a[3]), "r"(b[0]), "r"(b[1]));
}
__device__ __forceinline__ uint32_t pack_hi2(float x, float y) {
    unsigned short hx = __half_as_ushort(__float2half_rn(x));
    unsigned short hy = __half_as_ushort(__float2half_rn(y));
    return (uint32_t)hx | ((uint32_t)hy << 16);
}
__device__ __forceinline__ uint32_t pack_lo2(float x, float y) {
    float hx = __half2float(__float2half_rn(x));
    float hy = __half2float(__float2half_rn(y));
    unsigned short lx = __half_as_ushort(__float2half_rn(x - hx));
    unsigned short ly = __half_as_ushort(__float2half_rn(y - hy));
    return (uint32_t)lx | ((uint32_t)ly << 16);
}

// ---------------------------------------------------------------------------
// fp16-split GEMM via mma.sync, NT form: C[m,n] = sum_k A[m,k]*B[n,k].
// Block tile 128x256, BK=64, 512 threads (16 warps, warp tile 64x32),
// 2-stage cp.async. NPROD=3: AhBh+AhBl+AlBh. NPROD=2: AhBh+AhBl.
// EPI: 2 = logits (+cs[row] via add, +ct[col] via bias, mask->-1e18, f32)
//      3 = split hi/lo, no bias
//      5 = split hi only
//      6 = +bias[col] +add[row,col], f32
// ---------------------------------------------------------------------------
template <int EPI, int NPROD>
__global__ void __launch_bounds__(512, 1) gemm_mma(
    const __half* __restrict__ Ah, const __half* __restrict__ Al,
    const __half* __restrict__ Bh, const __half* __restrict__ Bl,
    int K, int Nt,
    long sA, long sB, long sC,
    const float* __restrict__ bias,
    const int* __restrict__ mask,
    const float* __restrict__ add,
    float* __restrict__ Cf,
    __half* __restrict__ Ch, __half* __restrict__ Cl)
{
    extern __shared__ __align__(16) char dsm[];
    constexpr uint32_t ROWB = 144;                      // 64 fp16 (128B) + 16B pad
    constexpr uint32_t OAH = 0;                         // A-hi: 128*144 = 18432
    constexpr uint32_t OAL = 18432;                     // A-lo (NPROD=3 only)
    constexpr uint32_t OBH = (NPROD == 3) ? 36864u : 18432u;
    constexpr uint32_t OBL = OBH + 36864;               // B tiles: 256*144
    constexpr uint32_t STAGE = OBL + 36864;             // 110592 or 92160

    const uint32_t smb = smem_u32(dsm);
    const int tid = threadIdx.x;
    const int lane = tid & 31;
    const int wid = tid >> 5;

    const int bm = blockIdx.y * 128;
    const int bn = blockIdx.x * 256;
    const long z = blockIdx.z;

    const __half* bAh = Ah + z * sA;
    const __half* bAl = (NPROD == 3) ? (Al + z * sA) : nullptr;
    const __half* bBh = Bh + z * sB;
    const __half* bBl = Bl + z * sB;

#define LOAD_STAGE(stg, k0) do {                                                             \
    uint32_t sb_ = smb + (uint32_t)(stg) * STAGE;                                            \
    _Pragma("unroll")                                                                        \
    for (int i_ = 0; i_ < 2; i_++) {                                                         \
        int id_ = tid + i_ * 512, rA_ = id_ >> 3, sA_ = id_ & 7;                             \
        CP16(sb_ + OAH + rA_ * ROWB + sA_ * 16, bAh + (size_t)(bm + rA_) * K + (k0) + sA_ * 8);\
        if (NPROD == 3)                                                                      \
            CP16(sb_ + OAL + rA_ * ROWB + sA_ * 16, bAl + (size_t)(bm + rA_) * K + (k0) + sA_ * 8);\
    }                                                                                        \
    _Pragma("unroll")                                                                        \
    for (int i_ = 0; i_ < 4; i_++) {                                                         \
        int id_ = tid + i_ * 512, rB_ = id_ >> 3, sB_ = id_ & 7;                             \
        CP16(sb_ + OBH + rB_ * ROWB + sB_ * 16, bBh + (size_t)(bn + rB_) * K + (k0) + sB_ * 8);\
        CP16(sb_ + OBL + rB_ * ROWB + sB_ * 16, bBl + (size_t)(bn + rB_) * K + (k0) + sB_ * 8);\
    }                                                                                        \
} while (0)

    float acc[4][4][4];
#pragma unroll
    for (int i = 0; i < 4; i++)
#pragma unroll
        for (int j = 0; j < 4; j++)
#pragma unroll
            for (int t = 0; t < 4; t++) acc[i][j][t] = 0.0f;

    const int nk = K >> 6;
    LOAD_STAGE(0, 0);
    CP_COMMIT();

    const int m0w = (wid & 1) * 64;      // 2 warps in M
    const int n0w = (wid >> 1) * 32;     // 8 warps in N
    const int lrow = lane & 15;
    const uint32_t lcb = (uint32_t)(lane >> 4) * 16;

    for (int c = 0; c < nk; c++) {
        CP_WAIT0();
        __syncthreads();
        if (c + 1 < nk) { LOAD_STAGE((c + 1) & 1, (c + 1) * 64); CP_COMMIT(); }

        const uint32_t sb = smb + (uint32_t)(c & 1) * STAGE;
#pragma unroll
        for (int s = 0; s < 4; s++) {
            const uint32_t kb = (uint32_t)s * 32 + lcb;

            if (NPROD == 3) {
                uint32_t ah[4][4], al[4][4];
#pragma unroll
                for (int mi = 0; mi < 4; mi++) {
                    ldsm4(ah[mi][0], ah[mi][1], ah[mi][2], ah[mi][3],
                          sb + OAH + (uint32_t)(m0w + 16 * mi + lrow) * ROWB + kb);
                    ldsm4(al[mi][0], al[mi][1], al[mi][2], al[mi][3],
                          sb + OAL + (uint32_t)(m0w + 16 * mi + lrow) * ROWB + kb);
                }
#pragma unroll
                for (int nj = 0; nj < 2; nj++) {
                    uint32_t t0, t1, t2, t3;
                    uint32_t b0[2], b1[2];
                    ldsm4(t0, t1, t2, t3,
                          sb + OBH + (uint32_t)(n0w + 16 * nj + lrow) * ROWB + kb);
                    b0[0] = t0; b0[1] = t2; b1[0] = t1; b1[1] = t3;
#pragma unroll
                    for (int mi = 0; mi < 4; mi++) mma16816(acc[mi][2*nj],   ah[mi], b0);
#pragma unroll
                    for (int mi = 0; mi < 4; mi++) mma16816(acc[mi][2*nj+1], ah[mi], b1);
#pragma unroll
                    for (int mi = 0; mi < 4; mi++) mma16816(acc[mi][2*nj],   al[mi], b0);
#pragma unroll
                    for (int mi = 0; mi < 4; mi++) mma16816(acc[mi][2*nj+1], al[mi], b1);
                    ldsm4(t0, t1, t2, t3,
                          sb + OBL + (uint32_t)(n0w + 16 * nj + lrow) * ROWB + kb);
                    b0[0] = t0; b0[1] = t2; b1[0] = t1; b1[1] = t3;
#pragma unroll
                    for (int mi = 0; mi < 4; mi++) mma16816(acc[mi][2*nj],   ah[mi], b0);
#pragma unroll
                    for (int mi = 0; mi < 4; mi++) mma16816(acc[mi][2*nj+1], ah[mi], b1);
                }
            } else {
                uint32_t ah[4][4];
#pragma unroll
                for (int mi = 0; mi < 4; mi++)
                    ldsm4(ah[mi][0], ah[mi][1], ah[mi][2], ah[mi][3],
                          sb + OAH + (uint32_t)(m0w + 16 * mi + lrow) * ROWB + kb);
#pragma unroll
                for (int nj = 0; nj < 2; nj++) {
                    uint32_t t0, t1, t2, t3;
                    uint32_t b0[2], b1[2];
                    ldsm4(t0, t1, t2, t3,
                          sb + OBH + (uint32_t)(n0w + 16 * nj + lrow) * ROWB + kb);
                    b0[0] = t0; b0[1] = t2; b1[0] = t1; b1[1] = t3;
#pragma unroll
                    for (int mi = 0; mi < 4; mi++) mma16816(acc[mi][2*nj],   ah[mi], b0);
#pragma unroll
                    for (int mi = 0; mi < 4; mi++) mma16816(acc[mi][2*nj+1], ah[mi], b1);
                    ldsm4(t0, t1, t2, t3,
                          sb + OBL + (uint32_t)(n0w + 16 * nj + lrow) * ROWB + kb);
                    b0[0] = t0; b0[1] = t2; b1[0] = t1; b1[1] = t3;
#pragma unroll
                    for (int mi = 0; mi < 4; mi++) mma16816(acc[mi][2*nj],   ah[mi], b0);
#pragma unroll
                    for (int mi = 0; mi < 4; mi++) mma16816(acc[mi][2*nj+1], ah[mi], b1);
                }
            }
        }
    }

    // ---------------- epilogue ----------------
    const int* maskz = (EPI == 2) ? (mask + z * sC) : nullptr;
    float* Cfz = Cf ? Cf + z * sC : nullptr;
    __half* Chz = Ch ? Ch + z * sC : nullptr;
    __half* Clz = Cl ? Cl + z * sC : nullptr;

#pragma unroll
    for (int mi = 0; mi < 4; mi++) {
#pragma unroll
        for (int ni = 0; ni < 4; ni++) {
            float* a = acc[mi][ni];
            const int r = bm + m0w + 16 * mi + (lane >> 2);
            const int cc = bn + n0w + 8 * ni + (lane & 3) * 2;
            float v0 = a[0], v1 = a[1], v2 = a[2], v3 = a[3];

            if (EPI == 2) {
                // bias = ct[z*T + col], add = cs[z*S + row]; then mask
                float2 ctv = *(const float2*)&bias[(size_t)z * Nt + cc];
                float cs0 = add[(size_t)z * 2048 + r];
                float cs8 = add[(size_t)z * 2048 + r + 8];
                v0 += cs0 + ctv.x; v1 += cs0 + ctv.y;
                v2 += cs8 + ctv.x; v3 += cs8 + ctv.y;
                int2 mA = *(const int2*)&maskz[(size_t)r * Nt + cc];
                int2 mB = *(const int2*)&maskz[(size_t)(r + 8) * Nt + cc];
                if (mA.x) v0 = -1e18f;
                if (mA.y) v1 = -1e18f;
                if (mB.x) v2 = -1e18f;
                if (mB.y) v3 = -1e18f;
            }
            if (EPI == 6) {
                float2 b = *(const float2*)&bias[cc];
                float2 aA = *(const float2*)&add[(size_t)r * Nt + cc];
                float2 aB = *(const float2*)&add[(size_t)(r + 8) * Nt + cc];
                v0 += b.x + aA.x; v1 += b.y + aA.y;
                v2 += b.x + aB.x; v3 += b.y + aB.y;
            }

            if (EPI == 3) {
                *(uint32_t*)&Chz[(size_t)r * Nt + cc]       = pack_hi2(v0, v1);
                *(uint32_t*)&Clz[(size_t)r * Nt + cc]       = pack_lo2(v0, v1);
                *(uint32_t*)&Chz[(size_t)(r + 8) * Nt + cc] = pack_hi2(v2, v3);
                *(uint32_t*)&Clz[(size_t)(r + 8) * Nt + cc] = pack_lo2(v2, v3);
            } else if (EPI == 5) {
                *(uint32_t*)&Chz[(size_t)r * Nt + cc]       = pack_hi2(v0, v1);
                *(uint32_t*)&Chz[(size_t)(r + 8) * Nt + cc] = pack_hi2(v2, v3);
            } else {
                *(float2*)&Cfz[(size_t)r * Nt + cc]       = make_float2(v0, v1);
                *(float2*)&Cfz[(size_t)(r + 8) * Nt + cc] = make_float2(v2, v3);
            }
        }
    }
}

// ---------------------------------------------------------------------------
// small fp32 GEMM 512x512x512: C[i,j] = sum_c A'[.]·B[c,j].
// TRANS_A=true:  C = A^T B   (A read [c,i])
// TRANS_A=false: C = A B     (A read [i,c])
// ---------------------------------------------------------------------------
template <bool TRANS_A>
__global__ void smallgemm_kernel(const float* __restrict__ A,
                                 const float* __restrict__ B,
                                 float* __restrict__ C)
{
    __shared__ float As[16][17], Bs[16][17];
    const int i0 = blockIdx.y * 16, j0 = blockIdx.x * 16;
    const int ti = threadIdx.y, tj = threadIdx.x;
    float acc = 0.0f;
    for (int c0 = 0; c0 < 512; c0 += 16) {
        As[ti][tj] = TRANS_A ? A[(c0 + ti) * 512 + i0 + tj]
                             : A[(i0 + ti) * 512 + c0 + tj];
        Bs[ti][tj] = B[(c0 + ti) * 512 + j0 + tj];
        __syncthreads();
#pragma unroll
        for (int k = 0; k < 16; k++)
            acc += (TRANS_A ? As[k][ti] : As[ti][k]) * Bs[k][tj];
        __syncthreads();
    }
    C[(i0 + ti) * 512 + j0 + tj] = acc;
}

// ---------------------------------------------------------------------------
// bias prep: w1 = Wk^T bq, wv2 = Wq^T bk, b2 = Wo bv, c0 = bq.bk
// ---------------------------------------------------------------------------
__global__ void prepbias_kernel(const float* __restrict__ Wq, const float* __restrict__ Wk,
                                const float* __restrict__ Wo,
                                const float* __restrict__ bq, const float* __restrict__ bk,
                                const float* __restrict__ bv,
                                float* __restrict__ w1, float* __restrict__ wv2,
                                float* __restrict__ b2, float* __restrict__ c0)
{
    const int zz = blockIdx.y;
    const int idx = blockIdx.x * 128 + threadIdx.x;
    if (zz == 0) {
        float s = 0.0f;
        for (int j = 0; j < 512; j++) s += bq[j] * Wk[j * 512 + idx];
        w1[idx] = s;
    } else if (zz == 1) {
        float s = 0.0f;
        for (int j = 0; j < 512; j++) s += bk[j] * Wq[j * 512 + idx];
        wv2[idx] = s;
    } else if (zz == 2) {
        float s = 0.0f;
        for (int j = 0; j < 512; j++) s += Wo[idx * 512 + j] * bv[j];
        b2[idx] = s;
    } else if (blockIdx.x == 0) {
        __shared__ float sh[4];
        float s = 0.0f;
        for (int j = threadIdx.x; j < 512; j += 128) s += bq[j] * bk[j];
#pragma unroll
        for (int o = 16; o > 0; o >>= 1) s += __shfl_xor_sync(0xffffffffu, s, o);
        if ((threadIdx.x & 31) == 0) sh[threadIdx.x >> 5] = s;
        __syncthreads();
        if (threadIdx.x == 0) c0[0] = sh[0] + sh[1] + sh[2] + sh[3];
    }
}

// ---------------------------------------------------------------------------
// rowdot: cs[r] = enc[r].wv2 + c0   (z=0) ; ct[r] = emo[r].w1   (z=1)
// one warp per row, 8 rows per block
// ---------------------------------------------------------------------------
__global__ void rowdot_kernel(const float* __restrict__ enc, const float* __restrict__ emo,
                              const float* __restrict__ wv2, const float* __restrict__ w1,
                              const float* __restrict__ c0,
                              float* __restrict__ cs, float* __restrict__ ct)
{
    const int zz = blockIdx.y;
    const float* src = zz ? emo : enc;
    const float* wv  = zz ? w1 : wv2;
    const int warp = threadIdx.x >> 5, lane = threadIdx.x & 31;
    const size_t r = (size_t)blockIdx.x * 8 + warp;
    const float4* p = (const float4*)(src + r * 512);
    const float4* w = (const float4*)wv;
    float s = 0.0f;
#pragma unroll
    for (int i = 0; i < 4; i++) {
        float4 a = p[lane + i * 32];
        float4 b = w[lane + i * 32];
        s += a.x * b.x + a.y * b.y + a.z * b.z + a.w * b.w;
    }
#pragma unroll
    for (int o = 16; o > 0; o >>= 1) s += __shfl_xor_sync(0xffffffffu, s, o);
    if (lane == 0) {
        if (zz) ct[r] = s;
        else    cs[r] = s + c0[0];
    }
}

// ---------------------------------------------------------------------------
// fp32 -> fp16 hi/lo split; z selects pair
// ---------------------------------------------------------------------------
__global__ void convsplit2_kernel(
    const float* __restrict__ x0, __half* __restrict__ h0, __half* __restrict__ l0,
    const float* __restrict__ x1, __half* __restrict__ h1, __half* __restrict__ l1)
{
    const float* x = (blockIdx.z == 0) ? x0 : x1;
    __half* h = (blockIdx.z == 0) ? h0 : h1;
    __half* l = (blockIdx.z == 0) ? l0 : l1;
    int i = (blockIdx.x * 256 + threadIdx.x) * 4;
    float4 v = *(const float4*)&x[i];
    *(uint32_t*)&h[i]     = pack_hi2(v.x, v.y);
    *(uint32_t*)&h[i + 2] = pack_hi2(v.z, v.w);
    *(uint32_t*)&l[i]     = pack_lo2(v.x, v.y);
    *(uint32_t*)&l[i + 2] = pack_lo2(v.z, v.w);
}

// ---------------------------------------------------------------------------
// x[T,E] fp32 (batched) -> xT hi/lo [E,T] fp16
// ---------------------------------------------------------------------------
__global__ void transconv_kernel(const float* __restrict__ v,
                                 __half* __restrict__ th,
                                 __half* __restrict__ tl)
{
    __shared__ float tile[32][33];
    const long z = blockIdx.z;
    const float* vz = v + z * ((size_t)T_ * E_);
    __half* thz = th + z * ((size_t)T_ * E_);
    __half* tlz = tl + z * ((size_t)T_ * E_);
    const int t0 = blockIdx.x * 32;
    const int e0 = blockIdx.y * 32;
    const int tx = threadIdx.x, ty = threadIdx.y;
#pragma unroll
    for (int i = 0; i < 32; i += 8)
        tile[ty + i][tx] = vz[(size_t)(t0 + ty + i) * E_ + e0 + tx];
    __syncthreads();
#pragma unroll
    for (int i = 0; i < 32; i += 8) {
        float x = tile[tx][ty + i];
        __half hi = __float2half_rn(x);
        size_t o = (size_t)(e0 + ty + i) * T_ + t0 + tx;
        thz[o] = hi;
        tlz[o] = __float2half_rn(x - __half2float(hi));
    }
}

// ---------------------------------------------------------------------------
// reductions
// ---------------------------------------------------------------------------
__device__ __forceinline__ float block_sum_256(float v) {
    __shared__ float sh[8];
    __shared__ float res;
#pragma unroll
    for (int o = 16; o > 0; o >>= 1) v += __shfl_xor_sync(0xffffffffu, v, o);
    const int w = threadIdx.x >> 5;
    if ((threadIdx.x & 31) == 0) sh[w] = v;
    __syncthreads();
    if (threadIdx.x == 0) {
        float t = 0.0f;
#pragma unroll
        for (int i = 0; i < 8; i++) t += sh[i];
        res = t;
    }
    __syncthreads();
    return res;
}
__device__ __forceinline__ float block_max_256(float v) {
    __shared__ float shm[8];
    __shared__ float resm;
#pragma unroll
    for (int o = 16; o > 0; o >>= 1) v = fmaxf(v, __shfl_xor_sync(0xffffffffu, v, o));
    const int w = threadIdx.x >> 5;
    if ((threadIdx.x & 31) == 0) shm[w] = v;
    __syncthreads();
    if (threadIdx.x == 0) {
        float t = shm[0];
#pragma unroll
        for (int i = 1; i < 8; i++) t = fmaxf(t, shm[i]);
        resm = t;
    }
    __syncthreads();
    return resm;
}

// ---------------------------------------------------------------------------
// softmax over T, emits fp16 weights (hi only)
// ---------------------------------------------------------------------------
__global__ void __launch_bounds__(256) softmax_split_kernel(
    const float* __restrict__ lg, __half* __restrict__ ph)
{
    const size_t base = (size_t)blockIdx.x * T_;
    const float* p = lg + base;
    const int t = threadIdx.x;
    float vals[8];
    float mx = -__int_as_float(0x7f800000);
#pragma unroll
    for (int i = 0; i < 8; i++) {
        vals[i] = p[t + i * 256];
        mx = fmaxf(mx, vals[i]);
    }
    mx = block_max_256(mx);
    float s = 0.0f;
#pragma unroll
    for (int i = 0; i < 8; i++) {
        vals[i] = __expf(vals[i] - mx);
        s += vals[i];
    }
    s = block_sum_256(s);
    const float inv = 1.0f / s;
#pragma unroll
    for (int i = 0; i < 8; i++)
        ph[base + t + i * 256] = __float2half_rn(vals[i] * inv);
}

// ---------------------------------------------------------------------------
// LayerNorm + residual
// ---------------------------------------------------------------------------
__global__ void __launch_bounds__(256) layernorm_kernel(
    const float* __restrict__ x, const float* __restrict__ enc,
    const float* __restrict__ gamma, const float* __restrict__ beta,
    float* __restrict__ out)
{
    const size_t row = blockIdx.x;
    const float* xr = x + row * E_;
    const float* er = enc + row * E_;
    float* orow = out + row * E_;
    const int t = threadIdx.x;

    const float x0 = xr[t];
    const float x1 = xr[t + 256];
    const float mean = block_sum_256(x0 + x1) * (1.0f / E_);
    const float d0 = x0 - mean;
    const float d1 = x1 - mean;
    const float var = block_sum_256(d0 * d0 + d1 * d1) * (1.0f / E_);
    const float inv = 1.0f / (sqrtf(var) + EPSF);

    orow[t]       = er[t]       + gamma[t]       * d0 * inv + beta[t];
    orow[t + 256] = er[t + 256] + gamma[t + 256] * d1 * inv + beta[t + 256];
}

// ---------------------------------------------------------------------------
// launch
// ---------------------------------------------------------------------------
extern "C" void kernel_launch(void* const* d_in, const int* in_sizes, int n_in,
                              void* d_out, int out_size)
{
    const float* enc  = (const float*)d_in[0];
    const float* emo  = (const float*)d_in[1];
    const int*   mask = (const int*)d_in[2];
    const float* Wq   = (const float*)d_in[3];
    const float* bq   = (const float*)d_in[4];
    const float* Wk   = (const float*)d_in[5];
    const float* bk   = (const float*)d_in[6];
    const float* Wv   = (const float*)d_in[7];
    const float* bv   = (const float*)d_in[8];
    const float* Wo   = (const float*)d_in[9];
    const float* gamma = (const float*)d_in[10];
    const float* beta  = (const float*)d_in[11];
    float* out = (float*)d_out;

    __half *encH,*encL,*emoH,*emoL,*NH,*NL,*W2H,*W2L,*UH,*UL,*eTH,*eTL,*pH,*YH;
    float *N, *W2, *w1, *wv2, *b2, *c0, *cs, *ct, *lg, *tmp;
    cudaGetSymbolAddress((void**)&encH, g_encH); cudaGetSymbolAddress((void**)&encL, g_encL);
    cudaGetSymbolAddress((void**)&emoH, g_emoH); cudaGetSymbolAddress((void**)&emoL, g_emoL);
    cudaGetSymbolAddress((void**)&N, g_N);       cudaGetSymbolAddress((void**)&W2, g_W2);
    cudaGetSymbolAddress((void**)&NH, g_NH);     cudaGetSymbolAddress((void**)&NL, g_NL);
    cudaGetSymbolAddress((void**)&W2H, g_W2H);   cudaGetSymbolAddress((void**)&W2L, g_W2L);
    cudaGetSymbolAddress((void**)&w1, g_w1);     cudaGetSymbolAddress((void**)&wv2, g_wv2);
    cudaGetSymbolAddress((void**)&b2, g_b2);     cudaGetSymbolAddress((void**)&c0, g_c0);
    cudaGetSymbolAddress((void**)&cs, g_cs);     cudaGetSymbolAddress((void**)&ct, g_ct);
    cudaGetSymbolAddress((void**)&UH, g_UH);     cudaGetSymbolAddress((void**)&UL, g_UL);
    cudaGetSymbolAddress((void**)&eTH, g_eTH);   cudaGetSymbolAddress((void**)&eTL, g_eTL);
    cudaGetSymbolAddress((void**)&pH, g_pH);     cudaGetSymbolAddress((void**)&YH, g_YH);
    cudaGetSymbolAddress((void**)&lg, g_logits); cudaGetSymbolAddress((void**)&tmp, g_tmp);

    const int SMEM3 = 2 * 110592;   // 221184 (NPROD=3)
    const int SMEM2 = 2 * 92160;    // 184320 (NPROD=2)
    cudaFuncSetAttribute(gemm_mma<3,3>, cudaFuncAttributeMaxDynamicSharedMemorySize, SMEM3);
    cudaFuncSetAttribute(gemm_mma<2,3>, cudaFuncAttributeMaxDynamicSharedMemorySize, SMEM3);
    cudaFuncSetAttribute(gemm_mma<5,2>, cudaFuncAttributeMaxDynamicSharedMemorySize, SMEM2);
    cudaFuncSetAttribute(gemm_mma<6,2>, cudaFuncAttributeMaxDynamicSharedMemorySize, SMEM2);

    // 1) input splits (enc + emo)
    convsplit2_kernel<<<dim3(NSE / 1024, 1, 2), 256>>>(enc, encH, encL, emo, emoH, emoL);

    // 2) N = Wk^T @ Wq  (for U = enc @ N^T = enc (Wq^T Wk))
    smallgemm_kernel<true><<<dim3(32, 32), dim3(16, 16)>>>(Wk, Wq, N);
    // 3) W2 = Wo @ Wv   (folds V proj + out proj)
    smallgemm_kernel<false><<<dim3(32, 32), dim3(16, 16)>>>(Wo, Wv, W2);
    // 4) split N, W2 to hi/lo
    convsplit2_kernel<<<dim3((E_*E_) / 1024, 1, 2), 256>>>(N, NH, NL, W2, W2H, W2L);

    // 5) U = enc @ N^T (3-product; error-critical) — profiled slot
    const dim3 gp(E_ / 256, (B_ * S_) / 128, 1);
    gemm_mma<3,3><<<gp, 512, SMEM3>>>(encH, encL, NH, NL, E_, E_, 0, 0, 0,
                                      nullptr, nullptr, nullptr, nullptr, UH, UL);

    // 6) bias prep + 7) row dots (exact bias handling; zeros in this dataset)
    prepbias_kernel<<<dim3(4, 4), 128>>>(Wq, Wk, Wo, bq, bk, bv, w1, wv2, b2, c0);
    rowdot_kernel<<<dim3((B_ * S_) / 8, 2), 256>>>(enc, emo, wv2, w1, c0, cs, ct);

    // 8) logits = U @ emo^T + cs + ct, masked (3-product)
    const dim3 gl(T_ / 256, S_ / 128, B_);
    gemm_mma<2,3><<<gl, 512, SMEM3>>>(UH, UL, emoH, emoL, E_, T_,
                                      (long)S_ * E_, (long)T_ * E_, (long)S_ * T_,
                                      ct, mask, cs, lg, nullptr, nullptr);

    // 9) emo -> emoT hi/lo (for Y = P @ emo)
    transconv_kernel<<<dim3(T_ / 32, E_ / 32, B_), dim3(32, 8)>>>(emo, eTH, eTL);

    // 10) softmax -> P hi (fp16)
    softmax_split_kernel<<<B_ * S_, 256>>>(lg, pH);

    // 11) Y = P @ emo  (2-product, hi-only out)
    const dim3 gc(E_ / 256, S_ / 128, B_);
    gemm_mma<5,2><<<gc, 512, SMEM2>>>(pH, nullptr, eTH, eTL, T_, E_,
                                      (long)S_ * T_, (long)T_ * E_, (long)S_ * E_,
                                      nullptr, nullptr, nullptr, nullptr, YH, nullptr);

    // 12) tmp = Y @ W2^T + b2 + enc (2-product)
    const dim3 go(E_ / 256, (B_ * S_) / 128, 1);
    gemm_mma<6,2><<<go, 512, SMEM2>>>(YH, nullptr, W2H, W2L, E_, E_, 0, 0, 0,
                                      b2, nullptr, enc, tmp, nullptr, nullptr);

    // 13) out = enc + LN(tmp)
    layernorm_kernel<<<B_ * S_, 256>>>(tmp, enc, gamma, beta, out);
}

// round 17
// speedup vs baseline: 1.1267x; 1.0318x over previous
#include <cuda_runtime.h>
#include <cuda_fp16.h>
#include <cstdint>

#define EPSF 1e-6f

constexpr int B_ = 8;
constexpr int S_ = 2048;
constexpr int T_ = 2048;
constexpr int E_ = 512;

constexpr int NSE = B_ * S_ * E_;               // 8388608
constexpr size_t NST = (size_t)B_ * S_ * T_;    // 33554432

// ---------------- scratch (device globals) ----------------
__device__ __half g_encH[NSE], g_encL[NSE];
__device__ __half g_emoH[NSE], g_emoL[NSE];
__device__ float  g_N[E_*E_], g_W2[E_*E_];
__device__ __half g_NH[E_*E_], g_NL[E_*E_];
__device__ __half g_W2H[E_*E_], g_W2L[E_*E_];
__device__ float  g_w1[E_], g_wv2[E_], g_b2[E_], g_c0[1];
__device__ float  g_cs[B_*S_], g_ct[B_*T_];
__device__ __half g_UH[NSE], g_UL[NSE];
__device__ __half g_eTH[NSE], g_eTL[NSE];
__device__ float  g_logits[NST];
__device__ __half g_pH[NST];
__device__ __half g_YH[NSE];
__device__ float  g_tmp[NSE];

// ---------------- helpers ----------------
__device__ __forceinline__ uint32_t smem_u32(const void* p) {
    uint32_t a;
    asm("{ .reg .u64 t; cvta.to.shared.u64 t, %1; cvt.u32.u64 %0, t; }" : "=r"(a) : "l"(p));
    return a;
}
#define CP16(dst, src) asm volatile("cp.async.cg.shared.global [%0], [%1], 16;" :: "r"(dst), "l"(src))
#define CP_COMMIT()    asm volatile("cp.async.commit_group;")
#define CP_WAIT0()     asm volatile("cp.async.wait_group 0;")

__device__ __forceinline__ void ldsm4(uint32_t& r0, uint32_t& r1, uint32_t& r2, uint32_t& r3, uint32_t a) {
    asm volatile("ldmatrix.sync.aligned.m8n8.x4.shared.b16 {%0,%1,%2,%3}, [%4];"
                 : "=r"(r0), "=r"(r1), "=r"(r2), "=r"(r3) : "r"(a));
}
__device__ __forceinline__ void mma16816(float* c, const uint32_t* a, const uint32_t* b) {
    asm volatile("mma.sync.aligned.m16n8k16.row.col.f32.f16.f16.f32 "
                 "{%0,%1,%2,%3}, {%4,%5,%6,%7}, {%8,%9}, {%0,%1,%2,%3};"
                 : "+f"(c[0]), "+f"(c[1]), "+f"(c[2]), "+f"(c[3])
                 : "r"(a[0]), "r"(a[1]), "r"(a[2]), "r"(a[3]), "r"(b[0]), "r"(b[1]));
}
__device__ __forceinline__ uint32_t pack_hi2(float x, float y) {
    unsigned short hx = __half_as_ushort(__float2half_rn(x));
    unsigned short hy = __half_as_ushort(__float2half_rn(y));
    return (uint32_t)hx | ((uint32_t)hy << 16);
}
__device__ __forceinline__ uint32_t pack_lo2(float x, float y) {
    float hx = __half2float(__float2half_rn(x));
    float hy = __half2float(__float2half_rn(y));
    unsigned short lx = __half_as_ushort(__float2half_rn(x - hx));
    unsigned short ly = __half_as_ushort(__float2half_rn(y - hy));
    return (uint32_t)lx | ((uint32_t)ly << 16);
}

// ---------------------------------------------------------------------------
// fp16-split GEMM via mma.sync, NT form: C[m,n] = sum_k A[m,k]*B[n,k].
// Block tile 128x256, BK=64, 512 threads (16 warps, warp tile 64x32),
// 2-stage cp.async. NPROD=3: AhBh+AhBl+AlBh. NPROD=2: AhBh+AhBl.
// EPI: 2 = logits (+cs[row], +ct[col], mask->-1e18, f32)
//      3 = split hi/lo   5 = split hi only   6 = +bias[col]+add[row,col], f32
// ---------------------------------------------------------------------------
template <int EPI, int NPROD>
__global__ void __launch_bounds__(512, 1) gemm_mma(
    const __half* __restrict__ Ah, const __half* __restrict__ Al,
    const __half* __restrict__ Bh, const __half* __restrict__ Bl,
    int K, int Nt,
    long sA, long sB, long sC,
    const float* __restrict__ bias,
    const int* __restrict__ mask,
    const float* __restrict__ add,
    float* __restrict__ Cf,
    __half* __restrict__ Ch, __half* __restrict__ Cl)
{
    extern __shared__ __align__(16) char dsm[];
    constexpr uint32_t ROWB = 144;                      // 64 fp16 (128B) + 16B pad
    constexpr uint32_t OAH = 0;
    constexpr uint32_t OAL = 18432;
    constexpr uint32_t OBH = (NPROD == 3) ? 36864u : 18432u;
    constexpr uint32_t OBL = OBH + 36864;
    constexpr uint32_t STAGE = OBL + 36864;             // 110592 or 92160

    const uint32_t smb = smem_u32(dsm);
    const int tid = threadIdx.x;
    const int lane = tid & 31;
    const int wid = tid >> 5;

    const int bm = blockIdx.y * 128;
    const int bn = blockIdx.x * 256;
    const long z = blockIdx.z;

    const __half* bAh = Ah + z * sA;
    const __half* bAl = (NPROD == 3) ? (Al + z * sA) : nullptr;
    const __half* bBh = Bh + z * sB;
    const __half* bBl = Bl + z * sB;

#define LOAD_STAGE(stg, k0) do {                                                             \
    uint32_t sb_ = smb + (uint32_t)(stg) * STAGE;                                            \
    _Pragma("unroll")                                                                        \
    for (int i_ = 0; i_ < 2; i_++) {                                                         \
        int id_ = tid + i_ * 512, rA_ = id_ >> 3, sA_ = id_ & 7;                             \
        CP16(sb_ + OAH + rA_ * ROWB + sA_ * 16, bAh + (size_t)(bm + rA_) * K + (k0) + sA_ * 8);\
        if (NPROD == 3)                                                                      \
            CP16(sb_ + OAL + rA_ * ROWB + sA_ * 16, bAl + (size_t)(bm + rA_) * K + (k0) + sA_ * 8);\
    }                                                                                        \
    _Pragma("unroll")                                                                        \
    for (int i_ = 0; i_ < 4; i_++) {                                                         \
        int id_ = tid + i_ * 512, rB_ = id_ >> 3, sB_ = id_ & 7;                             \
        CP16(sb_ + OBH + rB_ * ROWB + sB_ * 16, bBh + (size_t)(bn + rB_) * K + (k0) + sB_ * 8);\
        CP16(sb_ + OBL + rB_ * ROWB + sB_ * 16, bBl + (size_t)(bn + rB_) * K + (k0) + sB_ * 8);\
    }                                                                                        \
} while (0)

    float acc[4][4][4];
#pragma unroll
    for (int i = 0; i < 4; i++)
#pragma unroll
        for (int j = 0; j < 4; j++)
#pragma unroll
            for (int t = 0; t < 4; t++) acc[i][j][t] = 0.0f;

    const int nk = K >> 6;
    LOAD_STAGE(0, 0);
    CP_COMMIT();

    const int m0w = (wid & 1) * 64;      // 2 warps in M
    const int n0w = (wid >> 1) * 32;     // 8 warps in N
    const int lrow = lane & 15;
    const uint32_t lcb = (uint32_t)(lane >> 4) * 16;

    for (int c = 0; c < nk; c++) {
        CP_WAIT0();
        __syncthreads();
        if (c + 1 < nk) { LOAD_STAGE((c + 1) & 1, (c + 1) * 64); CP_COMMIT(); }

        const uint32_t sb = smb + (uint32_t)(c & 1) * STAGE;
#pragma unroll
        for (int s = 0; s < 4; s++) {
            const uint32_t kb = (uint32_t)s * 32 + lcb;

            if (NPROD == 3) {
                uint32_t ah[4][4], al[4][4];
#pragma unroll
                for (int mi = 0; mi < 4; mi++) {
                    ldsm4(ah[mi][0], ah[mi][1], ah[mi][2], ah[mi][3],
                          sb + OAH + (uint32_t)(m0w + 16 * mi + lrow) * ROWB + kb);
                    ldsm4(al[mi][0], al[mi][1], al[mi][2], al[mi][3],
                          sb + OAL + (uint32_t)(m0w + 16 * mi + lrow) * ROWB + kb);
                }
#pragma unroll
                for (int nj = 0; nj < 2; nj++) {
                    uint32_t t0, t1, t2, t3;
                    uint32_t b0[2], b1[2];
                    ldsm4(t0, t1, t2, t3,
                          sb + OBH + (uint32_t)(n0w + 16 * nj + lrow) * ROWB + kb);
                    b0[0] = t0; b0[1] = t2; b1[0] = t1; b1[1] = t3;
#pragma unroll
                    for (int mi = 0; mi < 4; mi++) mma16816(acc[mi][2*nj],   ah[mi], b0);
#pragma unroll
                    for (int mi = 0; mi < 4; mi++) mma16816(acc[mi][2*nj+1], ah[mi], b1);
#pragma unroll
                    for (int mi = 0; mi < 4; mi++) mma16816(acc[mi][2*nj],   al[mi], b0);
#pragma unroll
                    for (int mi = 0; mi < 4; mi++) mma16816(acc[mi][2*nj+1], al[mi], b1);
                    ldsm4(t0, t1, t2, t3,
                          sb + OBL + (uint32_t)(n0w + 16 * nj + lrow) * ROWB + kb);
                    b0[0] = t0; b0[1] = t2; b1[0] = t1; b1[1] = t3;
#pragma unroll
                    for (int mi = 0; mi < 4; mi++) mma16816(acc[mi][2*nj],   ah[mi], b0);
#pragma unroll
                    for (int mi = 0; mi < 4; mi++) mma16816(acc[mi][2*nj+1], ah[mi], b1);
                }
            } else {
                uint32_t ah[4][4];
#pragma unroll
                for (int mi = 0; mi < 4; mi++)
                    ldsm4(ah[mi][0], ah[mi][1], ah[mi][2], ah[mi][3],
                          sb + OAH + (uint32_t)(m0w + 16 * mi + lrow) * ROWB + kb);
#pragma unroll
                for (int nj = 0; nj < 2; nj++) {
                    uint32_t t0, t1, t2, t3;
                    uint32_t b0[2], b1[2];
                    ldsm4(t0, t1, t2, t3,
                          sb + OBH + (uint32_t)(n0w + 16 * nj + lrow) * ROWB + kb);
                    b0[0] = t0; b0[1] = t2; b1[0] = t1; b1[1] = t3;
#pragma unroll
                    for (int mi = 0; mi < 4; mi++) mma16816(acc[mi][2*nj],   ah[mi], b0);
#pragma unroll
                    for (int mi = 0; mi < 4; mi++) mma16816(acc[mi][2*nj+1], ah[mi], b1);
                    ldsm4(t0, t1, t2, t3,
                          sb + OBL + (uint32_t)(n0w + 16 * nj + lrow) * ROWB + kb);
                    b0[0] = t0; b0[1] = t2; b1[0] = t1; b1[1] = t3;
#pragma unroll
                    for (int mi = 0; mi < 4; mi++) mma16816(acc[mi][2*nj],   ah[mi], b0);
#pragma unroll
                    for (int mi = 0; mi < 4; mi++) mma16816(acc[mi][2*nj+1], ah[mi], b1);
                }
            }
        }
    }

    // ---------------- epilogue ----------------
    const int* maskz = (EPI == 2) ? (mask + z * sC) : nullptr;
    float* Cfz = Cf ? Cf + z * sC : nullptr;
    __half* Chz = Ch ? Ch + z * sC : nullptr;
    __half* Clz = Cl ? Cl + z * sC : nullptr;

#pragma unroll
    for (int mi = 0; mi < 4; mi++) {
#pragma unroll
        for (int ni = 0; ni < 4; ni++) {
            float* a = acc[mi][ni];
            const int r = bm + m0w + 16 * mi + (lane >> 2);
            const int cc = bn + n0w + 8 * ni + (lane & 3) * 2;
            float v0 = a[0], v1 = a[1], v2 = a[2], v3 = a[3];

            if (EPI == 2) {
                float2 ctv = *(const float2*)&bias[(size_t)z * Nt + cc];
                float cs0 = add[(size_t)z * 2048 + r];
                float cs8 = add[(size_t)z * 2048 + r + 8];
                v0 += cs0 + ctv.x; v1 += cs0 + ctv.y;
                v2 += cs8 + ctv.x; v3 += cs8 + ctv.y;
                int2 mA = *(const int2*)&maskz[(size_t)r * Nt + cc];
                int2 mB = *(const int2*)&maskz[(size_t)(r + 8) * Nt + cc];
                if (mA.x) v0 = -1e18f;
                if (mA.y) v1 = -1e18f;
                if (mB.x) v2 = -1e18f;
                if (mB.y) v3 = -1e18f;
            }
            if (EPI == 6) {
                float2 b = *(const float2*)&bias[cc];
                float2 aA = *(const float2*)&add[(size_t)r * Nt + cc];
                float2 aB = *(const float2*)&add[(size_t)(r + 8) * Nt + cc];
                v0 += b.x + aA.x; v1 += b.y + aA.y;
                v2 += b.x + aB.x; v3 += b.y + aB.y;
            }

            if (EPI == 3) {
                *(uint32_t*)&Chz[(size_t)r * Nt + cc]       = pack_hi2(v0, v1);
                *(uint32_t*)&Clz[(size_t)r * Nt + cc]       = pack_lo2(v0, v1);
                *(uint32_t*)&Chz[(size_t)(r + 8) * Nt + cc] = pack_hi2(v2, v3);
                *(uint32_t*)&Clz[(size_t)(r + 8) * Nt + cc] = pack_lo2(v2, v3);
            } else if (EPI == 5) {
                *(uint32_t*)&Chz[(size_t)r * Nt + cc]       = pack_hi2(v0, v1);
                *(uint32_t*)&Chz[(size_t)(r + 8) * Nt + cc] = pack_hi2(v2, v3);
            } else {
                *(float2*)&Cfz[(size_t)r * Nt + cc]       = make_float2(v0, v1);
                *(float2*)&Cfz[(size_t)(r + 8) * Nt + cc] = make_float2(v2, v3);
            }
        }
    }
}

// ---------------------------------------------------------------------------
// fp32 512^3 GEMM pair, one launch. z=0: N = Wk^T @ Wq. z=1: W2 = Wo @ Wv.
// 64x64 block tile, 256 threads, 4x4 micro-tile, BK=16.
// ---------------------------------------------------------------------------
__global__ void __launch_bounds__(256) smallgemm2_kernel(
    const float* __restrict__ Wq, const float* __restrict__ Wk,
    const float* __restrict__ Wv, const float* __restrict__ Wo,
    float* __restrict__ N, float* __restrict__ W2)
{
    __shared__ float As[16][68], Bs[16][68];
    const bool trans = (blockIdx.z == 0);
    const float* A = trans ? Wk : Wo;
    const float* Bm = trans ? Wq : Wv;
    float* C = trans ? N : W2;

    const int i0 = blockIdx.y * 64, j0 = blockIdx.x * 64;
    const int tid = threadIdx.x;
    const int ti = tid >> 4, tj = tid & 15;     // 16x16 thread grid

    float acc[4][4];
#pragma unroll
    for (int a = 0; a < 4; a++)
#pragma unroll
        for (int b = 0; b < 4; b++) acc[a][b] = 0.0f;

    for (int c0 = 0; c0 < 512; c0 += 16) {
        // load A tile -> As[k][i] (64 wide)
        if (trans) {
#pragma unroll
            for (int e = 0; e < 4; e++) {
                int id = tid + e * 256, ii = id & 63, kk = id >> 6;
                As[kk][ii] = A[(c0 + kk) * 512 + i0 + ii];
            }
        } else {
#pragma unroll
            for (int e = 0; e < 4; e++) {
                int id = tid + e * 256, cc = id & 15, ii = id >> 4;
                As[cc][ii] = A[(i0 + ii) * 512 + c0 + cc];
            }
        }
        // load B tile -> Bs[k][j]
#pragma unroll
        for (int e = 0; e < 4; e++) {
            int id = tid + e * 256, jj = id & 63, kk = id >> 6;
            Bs[kk][jj] = Bm[(c0 + kk) * 512 + j0 + jj];
        }
        __syncthreads();
#pragma unroll
        for (int k = 0; k < 16; k++) {
            float a[4], b[4];
#pragma unroll
            for (int r = 0; r < 4; r++) a[r] = As[k][ti * 4 + r];
#pragma unroll
            for (int r = 0; r < 4; r++) b[r] = Bs[k][tj * 4 + r];
#pragma unroll
            for (int x = 0; x < 4; x++)
#pragma unroll
                for (int y = 0; y < 4; y++) acc[x][y] += a[x] * b[y];
        }
        __syncthreads();
    }

#pragma unroll
    for (int x = 0; x < 4; x++)
#pragma unroll
        for (int y = 0; y < 4; y++)
            C[(size_t)(i0 + ti * 4 + x) * 512 + j0 + tj * 4 + y] = acc[x][y];
}

// ---------------------------------------------------------------------------
// bias prep: w1 = Wk^T bq, wv2 = Wq^T bk, b2 = Wo bv, c0 = bq.bk
// ---------------------------------------------------------------------------
__global__ void prepbias_kernel(const float* __restrict__ Wq, const float* __restrict__ Wk,
                                const float* __restrict__ Wo,
                                const float* __restrict__ bq, const float* __restrict__ bk,
                                const float* __restrict__ bv,
                                float* __restrict__ w1, float* __restrict__ wv2,
                                float* __restrict__ b2, float* __restrict__ c0)
{
    const int zz = blockIdx.y;
    const int idx = blockIdx.x * 128 + threadIdx.x;
    if (zz == 0) {
        float s = 0.0f;
        for (int j = 0; j < 512; j++) s += bq[j] * Wk[j * 512 + idx];
        w1[idx] = s;
    } else if (zz == 1) {
        float s = 0.0f;
        for (int j = 0; j < 512; j++) s += bk[j] * Wq[j * 512 + idx];
        wv2[idx] = s;
    } else if (zz == 2) {
        float s = 0.0f;
        for (int j = 0; j < 512; j++) s += Wo[idx * 512 + j] * bv[j];
        b2[idx] = s;
    } else if (blockIdx.x == 0) {
        __shared__ float sh[4];
        float s = 0.0f;
        for (int j = threadIdx.x; j < 512; j += 128) s += bq[j] * bk[j];
#pragma unroll
        for (int o = 16; o > 0; o >>= 1) s += __shfl_xor_sync(0xffffffffu, s, o);
        if ((threadIdx.x & 31) == 0) sh[threadIdx.x >> 5] = s;
        __syncthreads();
        if (threadIdx.x == 0) c0[0] = sh[0] + sh[1] + sh[2] + sh[3];
    }
}

// ---------------------------------------------------------------------------
// rowdot: cs[r] = enc[r].wv2 + c0   (z=0) ; ct[r] = emo[r].w1   (z=1)
// ---------------------------------------------------------------------------
__global__ void rowdot_kernel(const float* __restrict__ enc, const float* __restrict__ emo,
                              const float* __restrict__ wv2, const float* __restrict__ w1,
                              const float* __restrict__ c0,
                              float* __restrict__ cs, float* __restrict__ ct)
{
    const int zz = blockIdx.y;
    const float* src = zz ? emo : enc;
    const float* wv  = zz ? w1 : wv2;
    const int warp = threadIdx.x >> 5, lane = threadIdx.x & 31;
    const size_t r = (size_t)blockIdx.x * 8 + warp;
    const float4* p = (const float4*)(src + r * 512);
    const float4* w = (const float4*)wv;
    float s = 0.0f;
#pragma unroll
    for (int i = 0; i < 4; i++) {
        float4 a = p[lane + i * 32];
        float4 b = w[lane + i * 32];
        s += a.x * b.x + a.y * b.y + a.z * b.z + a.w * b.w;
    }
#pragma unroll
    for (int o = 16; o > 0; o >>= 1) s += __shfl_xor_sync(0xffffffffu, s, o);
    if (lane == 0) {
        if (zz) ct[r] = s;
        else    cs[r] = s + c0[0];
    }
}

// ---------------------------------------------------------------------------
// fp32 -> fp16 hi/lo split; z selects pair
// ---------------------------------------------------------------------------
__global__ void convsplit2_kernel(
    const float* __restrict__ x0, __half* __restrict__ h0, __half* __restrict__ l0,
    const float* __restrict__ x1, __half* __restrict__ h1, __half* __restrict__ l1)
{
    const float* x = (blockIdx.z == 0) ? x0 : x1;
    __half* h = (blockIdx.z == 0) ? h0 : h1;
    __half* l = (blockIdx.z == 0) ? l0 : l1;
    int i = (blockIdx.x * 256 + threadIdx.x) * 4;
    float4 v = *(const float4*)&x[i];
    *(uint32_t*)&h[i]     = pack_hi2(v.x, v.y);
    *(uint32_t*)&h[i + 2] = pack_hi2(v.z, v.w);
    *(uint32_t*)&l[i]     = pack_lo2(v.x, v.y);
    *(uint32_t*)&l[i + 2] = pack_lo2(v.z, v.w);
}

// ---------------------------------------------------------------------------
// x[T,E] fp32 (batched) -> xT hi/lo [E,T] fp16
// ---------------------------------------------------------------------------
__global__ void transconv_kernel(const float* __restrict__ v,
                                 __half* __restrict__ th,
                                 __half* __restrict__ tl)
{
    __shared__ float tile[32][33];
    const long z = blockIdx.z;
    const float* vz = v + z * ((size_t)T_ * E_);
    __half* thz = th + z * ((size_t)T_ * E_);
    __half* tlz = tl + z * ((size_t)T_ * E_);
    const int t0 = blockIdx.x * 32;
    const int e0 = blockIdx.y * 32;
    const int tx = threadIdx.x, ty = threadIdx.y;
#pragma unroll
    for (int i = 0; i < 32; i += 8)
        tile[ty + i][tx] = vz[(size_t)(t0 + ty + i) * E_ + e0 + tx];
    __syncthreads();
#pragma unroll
    for (int i = 0; i < 32; i += 8) {
        float x = tile[tx][ty + i];
        __half hi = __float2half_rn(x);
        size_t o = (size_t)(e0 + ty + i) * T_ + t0 + tx;
        thz[o] = hi;
        tlz[o] = __float2half_rn(x - __half2float(hi));
    }
}

// ---------------------------------------------------------------------------
// reductions
// ---------------------------------------------------------------------------
__device__ __forceinline__ float block_sum_256(float v) {
    __shared__ float sh[8];
    __shared__ float res;
#pragma unroll
    for (int o = 16; o > 0; o >>= 1) v += __shfl_xor_sync(0xffffffffu, v, o);
    const int w = threadIdx.x >> 5;
    if ((threadIdx.x & 31) == 0) sh[w] = v;
    __syncthreads();
    if (threadIdx.x == 0) {
        float t = 0.0f;
#pragma unroll
        for (int i = 0; i < 8; i++) t += sh[i];
        res = t;
    }
    __syncthreads();
    return res;
}
__device__ __forceinline__ float block_max_256(float v) {
    __shared__ float shm[8];
    __shared__ float resm;
#pragma unroll
    for (int o = 16; o > 0; o >>= 1) v = fmaxf(v, __shfl_xor_sync(0xffffffffu, v, o));
    const int w = threadIdx.x >> 5;
    if ((threadIdx.x & 31) == 0) shm[w] = v;
    __syncthreads();
    if (threadIdx.x == 0) {
        float t = shm[0];
#pragma unroll
        for (int i = 1; i < 8; i++) t = fmaxf(t, shm[i]);
        resm = t;
    }
    __syncthreads();
    return resm;
}

// ---------------------------------------------------------------------------
// softmax over T, emits fp16 weights (hi only)
// ---------------------------------------------------------------------------
__global__ void __launch_bounds__(256) softmax_split_kernel(
    const float* __restrict__ lg, __half* __restrict__ ph)
{
    const size_t base = (size_t)blockIdx.x * T_;
    const float* p = lg + base;
    const int t = threadIdx.x;
    float vals[8];
    float mx = -__int_as_float(0x7f800000);
#pragma unroll
    for (int i = 0; i < 8; i++) {
        vals[i] = p[t + i * 256];
        mx = fmaxf(mx, vals[i]);
    }
    mx = block_max_256(mx);
    float s = 0.0f;
#pragma unroll
    for (int i = 0; i < 8; i++) {
        vals[i] = __expf(vals[i] - mx);
        s += vals[i];
    }
    s = block_sum_256(s);
    const float inv = 1.0f / s;
#pragma unroll
    for (int i = 0; i < 8; i++)
        ph[base + t + i * 256] = __float2half_rn(vals[i] * inv);
}

// ---------------------------------------------------------------------------
// LayerNorm + residual
// ---------------------------------------------------------------------------
__global__ void __launch_bounds__(256) layernorm_kernel(
    const float* __restrict__ x, const float* __restrict__ enc,
    const float* __restrict__ gamma, const float* __restrict__ beta,
    float* __restrict__ out)
{
    const size_t row = blockIdx.x;
    const float* xr = x + row * E_;
    const float* er = enc + row * E_;
    float* orow = out + row * E_;
    const int t = threadIdx.x;

    const float x0 = xr[t];
    const float x1 = xr[t + 256];
    const float mean = block_sum_256(x0 + x1) * (1.0f / E_);
    const float d0 = x0 - mean;
    const float d1 = x1 - mean;
    const float var = block_sum_256(d0 * d0 + d1 * d1) * (1.0f / E_);
    const float inv = 1.0f / (sqrtf(var) + EPSF);

    orow[t]       = er[t]       + gamma[t]       * d0 * inv + beta[t];
    orow[t + 256] = er[t + 256] + gamma[t + 256] * d1 * inv + beta[t + 256];
}

// ---------------------------------------------------------------------------
// launch
// ---------------------------------------------------------------------------
extern "C" void kernel_launch(void* const* d_in, const int* in_sizes, int n_in,
                              void* d_out, int out_size)
{
    const float* enc  = (const float*)d_in[0];
    const float* emo  = (const float*)d_in[1];
    const int*   mask = (const int*)d_in[2];
    const float* Wq   = (const float*)d_in[3];
    const float* bq   = (const float*)d_in[4];
    const float* Wk   = (const float*)d_in[5];
    const float* bk   = (const float*)d_in[6];
    const float* Wv   = (const float*)d_in[7];
    const float* bv   = (const float*)d_in[8];
    const float* Wo   = (const float*)d_in[9];
    const float* gamma = (const float*)d_in[10];
    const float* beta  = (const float*)d_in[11];
    float* out = (float*)d_out;

    __half *encH,*encL,*emoH,*emoL,*NH,*NL,*W2H,*W2L,*UH,*UL,*eTH,*eTL,*pH,*YH;
    float *N, *W2, *w1, *wv2, *b2, *c0, *cs, *ct, *lg, *tmp;
    cudaGetSymbolAddress((void**)&encH, g_encH); cudaGetSymbolAddress((void**)&encL, g_encL);
    cudaGetSymbolAddress((void**)&emoH, g_emoH); cudaGetSymbolAddress((void**)&emoL, g_emoL);
    cudaGetSymbolAddress((void**)&N, g_N);       cudaGetSymbolAddress((void**)&W2, g_W2);
    cudaGetSymbolAddress((void**)&NH, g_NH);     cudaGetSymbolAddress((void**)&NL, g_NL);
    cudaGetSymbolAddress((void**)&W2H, g_W2H);   cudaGetSymbolAddress((void**)&W2L, g_W2L);
    cudaGetSymbolAddress((void**)&w1, g_w1);     cudaGetSymbolAddress((void**)&wv2, g_wv2);
    cudaGetSymbolAddress((void**)&b2, g_b2);     cudaGetSymbolAddress((void**)&c0, g_c0);
    cudaGetSymbolAddress((void**)&cs, g_cs);     cudaGetSymbolAddress((void**)&ct, g_ct);
    cudaGetSymbolAddress((void**)&UH, g_UH);     cudaGetSymbolAddress((void**)&UL, g_UL);
    cudaGetSymbolAddress((void**)&eTH, g_eTH);   cudaGetSymbolAddress((void**)&eTL, g_eTL);
    cudaGetSymbolAddress((void**)&pH, g_pH);     cudaGetSymbolAddress((void**)&YH, g_YH);
    cudaGetSymbolAddress((void**)&lg, g_logits); cudaGetSymbolAddress((void**)&tmp, g_tmp);

    const int SMEM3 = 2 * 110592;   // 221184 (NPROD=3)
    const int SMEM2 = 2 * 92160;    // 184320 (NPROD=2)
    cudaFuncSetAttribute(gemm_mma<3,3>, cudaFuncAttributeMaxDynamicSharedMemorySize, SMEM3);
    cudaFuncSetAttribute(gemm_mma<2,3>, cudaFuncAttributeMaxDynamicSharedMemorySize, SMEM3);
    cudaFuncSetAttribute(gemm_mma<5,2>, cudaFuncAttributeMaxDynamicSharedMemorySize, SMEM2);
    cudaFuncSetAttribute(gemm_mma<6,2>, cudaFuncAttributeMaxDynamicSharedMemorySize, SMEM2);

    // 1) input splits (enc + emo)
    convsplit2_kernel<<<dim3(NSE / 1024, 1, 2), 256>>>(enc, encH, encL, emo, emoH, emoL);

    // 2) N = Wk^T Wq and W2 = Wo Wv in one launch (64x64 tiles, 4x4 micro)
    smallgemm2_kernel<<<dim3(8, 8, 2), 256>>>(Wq, Wk, Wv, Wo, N, W2);

    // 3) split N, W2 to hi/lo
    convsplit2_kernel<<<dim3((E_*E_) / 1024, 1, 2), 256>>>(N, NH, NL, W2, W2H, W2L);

    // 4) U = enc @ N^T (3-product; error-critical)
    const dim3 gp(E_ / 256, (B_ * S_) / 128, 1);
    gemm_mma<3,3><<<gp, 512, SMEM3>>>(encH, encL, NH, NL, E_, E_, 0, 0, 0,
                                      nullptr, nullptr, nullptr, nullptr, UH, UL);

    // 5) bias prep + 6) row dots (exact bias handling)
    prepbias_kernel<<<dim3(4, 4), 128>>>(Wq, Wk, Wo, bq, bk, bv, w1, wv2, b2, c0);
    rowdot_kernel<<<dim3((B_ * S_) / 8, 2), 256>>>(enc, emo, wv2, w1, c0, cs, ct);

    // 7) logits = U @ emo^T + cs + ct, masked (3-product)
    const dim3 gl(T_ / 256, S_ / 128, B_);
    gemm_mma<2,3><<<gl, 512, SMEM3>>>(UH, UL, emoH, emoL, E_, T_,
                                      (long)S_ * E_, (long)T_ * E_, (long)S_ * T_,
                                      ct, mask, cs, lg, nullptr, nullptr);

    // 8) emo -> emoT hi/lo (for Y = P @ emo)
    transconv_kernel<<<dim3(T_ / 32, E_ / 32, B_), dim3(32, 8)>>>(emo, eTH, eTL);

    // 9) softmax -> P hi (fp16)
    softmax_split_kernel<<<B_ * S_, 256>>>(lg, pH);

    // 10) Y = P @ emo  (2-product, hi-only out)
    const dim3 gc(E_ / 256, S_ / 128, B_);
    gemm_mma<5,2><<<gc, 512, SMEM2>>>(pH, nullptr, eTH, eTL, T_, E_,
                                      (long)S_ * T_, (long)T_ * E_, (long)S_ * E_,
                                      nullptr, nullptr, nullptr, nullptr, YH, nullptr);

    // 11) tmp = Y @ W2^T + b2 + enc (2-product)
    const dim3 go(E_ / 256, (B_ * S_) / 128, 1);
    gemm_mma<6,2><<<go, 512, SMEM2>>>(YH, nullptr, W2H, W2L, E_, E_, 0, 0, 0,
                                      b2, nullptr, enc, tmp, nullptr, nullptr);

    // 12) out = enc + LN(tmp)
    layernorm_kernel<<<B_ * S_, 256>>>(tmp, enc, gamma, beta, out);
}